// round 5
// baseline (speedup 1.0000x reference)
#include <cuda_runtime.h>
#include <math.h>

#define B_ 8
#define L_ 2048
#define E_ 512
#define D_ 64
#define HH 64
#define WW 64
#define HW 4096
#define STEPS_ 5

typedef unsigned long long u64;

// packed fp32x2 helpers (sm_103a FFMA2 — only reachable via PTX)
__device__ __forceinline__ u64 dup2(float x) {
    u64 r; asm("mov.b64 %0, {%1, %1};" : "=l"(r) : "f"(x)); return r;
}
__device__ __forceinline__ void fma2(u64& d, u64 a, u64 b) {
    asm("fma.rn.f32x2 %0, %1, %2, %0;" : "+l"(d) : "l"(a), "l"(b));
}
__device__ __forceinline__ float2 f2u(u64 v) {
    float2 f; asm("mov.b64 {%0, %1}, %2;" : "=f"(f.x), "=f"(f.y) : "l"(v)); return f;
}

// ---------------- scratch (device globals; no allocation) ----------------
__device__ float g_gyi[B_*L_*HH];
__device__ float g_gxi[B_*L_*WW];
__device__ float g_gyo[B_*L_*HH];
__device__ float g_gxo[B_*L_*WW];
__device__ float g_proj[B_*L_*D_];
__device__ float g_field[B_*D_*HW];     // buffer A
__device__ float g_field2[B_*D_*HW];    // buffer B
__device__ float g_sampled[B_*L_*D_];

// ---------------- K0: separable gaussians + normalizers ----------------
__global__ void k_gauss(const float* __restrict__ pos,
                        const float* __restrict__ log_sigma) {
    int bl = blockIdx.x;
    int t  = threadIdx.x;   // 0..63
    float ls = *log_sigma;
    float si = log1pf(expf(ls)) + 1e-6f;
    float so = 2.0f * si;
    float i2si = 1.0f / (2.0f * si * si);
    float i2so = 1.0f / (2.0f * so * so);
    float py = pos[bl*2+0];
    float px = pos[bl*2+1];
    float d  = (float)t;
    float dy2 = (d - py) * (d - py);
    float dx2 = (d - px) * (d - px);
    float gy  = expf(-dy2 * i2si);
    float gx  = expf(-dx2 * i2si);
    float gyo = expf(-dy2 * i2so);
    float gxo = expf(-dx2 * i2so);
    __shared__ float red[4][64];
    __shared__ float sums[4];
    red[0][t]=gy; red[1][t]=gx; red[2][t]=gyo; red[3][t]=gxo;
    __syncthreads();
    if (t < 4) {
        float s = 0.0f;
        #pragma unroll
        for (int i = 0; i < 64; i++) s += red[t][i];
        sums[t] = s;
    }
    __syncthreads();
    float inv_ni = 1.0f / (sums[0]*sums[1] + 1e-6f);
    float inv_no = 1.0f / (sums[2]*sums[3] + 1e-6f);
    int base = bl*64 + t;
    g_gyi[base] = gy  * inv_ni;
    g_gxi[base] = gx;
    g_gyo[base] = gyo * inv_no;
    g_gxo[base] = gxo;
}

// ---------------- K1: proj = tokens @ W_to_field^T  (16384x64, K=512) ----
__global__ void __launch_bounds__(256)
k_proj(const float* __restrict__ tokens, const float* __restrict__ Wt) {
    __shared__ float As[32][132];   // [e][m]
    __shared__ float Bs[32][68];    // [e][d]
    int m0 = blockIdx.x * 128;
    int tx = threadIdx.x;
    int m_base = (tx >> 4) * 8;
    int n_base = (tx & 15) * 4;
    u64 acc[4][4] = {};             // [m_pair][n]
    for (int k0 = 0; k0 < 512; k0 += 32) {
        for (int i = tx; i < 32*128; i += 256) {
            int e = i & 31, m = i >> 5;
            As[e][m] = tokens[(m0+m)*512 + k0 + e];
        }
        for (int i = tx; i < 32*64; i += 256) {
            int e = i & 31, dch = i >> 5;
            Bs[e][dch] = Wt[dch*512 + k0 + e];
        }
        __syncthreads();
        #pragma unroll 4
        for (int kk = 0; kk < 32; kk++) {
            ulonglong2 a01 = *(const ulonglong2*)&As[kk][m_base];
            ulonglong2 a23 = *(const ulonglong2*)&As[kk][m_base+4];
            u64 ap[4] = {a01.x, a01.y, a23.x, a23.y};
            float4 bv = *(const float4*)&Bs[kk][n_base];
            u64 bd[4] = {dup2(bv.x), dup2(bv.y), dup2(bv.z), dup2(bv.w)};
            #pragma unroll
            for (int p = 0; p < 4; p++)
                #pragma unroll
                for (int j = 0; j < 4; j++)
                    fma2(acc[p][j], ap[p], bd[j]);
        }
        __syncthreads();
    }
    #pragma unroll
    for (int p = 0; p < 4; p++) {
        float2 q0 = f2u(acc[p][0]), q1 = f2u(acc[p][1]);
        float2 q2 = f2u(acc[p][2]), q3 = f2u(acc[p][3]);
        int m = m0 + m_base + 2*p;
        *(float4*)&g_proj[(size_t)m*64 + n_base]     = make_float4(q0.x,q1.x,q2.x,q3.x);
        *(float4*)&g_proj[(size_t)(m+1)*64 + n_base] = make_float4(q0.y,q1.y,q2.y,q3.y);
    }
}

// ------- K2: scatter. field[b](64 x 4096) = proj^T * (gy ⊗ gx) ---------
__global__ void __launch_bounds__(256) k_scatter() {
    __shared__ float As[32][68];    // [k=l][c]
    __shared__ float Bs[32][132];   // [k][n=hw]
    int b  = blockIdx.y;
    int n0 = blockIdx.x * 128;
    int h0 = n0 >> 6;
    int tx = threadIdx.x;
    int m_base = (tx >> 5) * 8;
    int n_base = (tx & 31) * 4;
    u64 acc[4][4] = {};             // [c_pair][n]
    for (int l0 = 0; l0 < L_; l0 += 32) {
        for (int i = tx; i < 32*64; i += 256) {
            int c = i & 63, k = i >> 6;
            As[k][c] = g_proj[((size_t)(b*L_) + l0 + k)*64 + c];
        }
        for (int i = tx; i < 32*128; i += 256) {
            int n = i & 127, k = i >> 7;
            int l = l0 + k;
            float gy = g_gyi[(b*L_+l)*64 + h0 + (n >> 6)];
            float gx = g_gxi[(b*L_+l)*64 + (n & 63)];
            Bs[k][n] = gy * gx;
        }
        __syncthreads();
        #pragma unroll 4
        for (int kk = 0; kk < 32; kk++) {
            ulonglong2 a01 = *(const ulonglong2*)&As[kk][m_base];
            ulonglong2 a23 = *(const ulonglong2*)&As[kk][m_base+4];
            u64 ap[4] = {a01.x, a01.y, a23.x, a23.y};
            float4 bv = *(const float4*)&Bs[kk][n_base];
            u64 bd[4] = {dup2(bv.x), dup2(bv.y), dup2(bv.z), dup2(bv.w)};
            #pragma unroll
            for (int p = 0; p < 4; p++)
                #pragma unroll
                for (int j = 0; j < 4; j++)
                    fma2(acc[p][j], ap[p], bd[j]);
        }
        __syncthreads();
    }
    #pragma unroll
    for (int p = 0; p < 4; p++) {
        float2 q0 = f2u(acc[p][0]), q1 = f2u(acc[p][1]);
        float2 q2 = f2u(acc[p][2]), q3 = f2u(acc[p][3]);
        int c = m_base + 2*p;
        *(float4*)&g_field[((size_t)(b*64) + c)*HW + n0 + n_base]
            = make_float4(q0.x,q1.x,q2.x,q3.x);
        *(float4*)&g_field[((size_t)(b*64) + c+1)*HW + n0 + n_base]
            = make_float4(q0.y,q1.y,q2.y,q3.y);
    }
}

// ---- K3: fused conv step.  out = in + conv2(relu(conv1(in))) ----
#define SM_HB 0
#define SM_AS (128*132)
#define SM_BS (128*132 + 36*132)
#define SM_TOTAL_FLOATS (128*132 + 2*36*132)

__global__ void __launch_bounds__(256, 2)
k_step(const float* __restrict__ w1, const float* __restrict__ bias1,
       const float* __restrict__ w2, const float* __restrict__ bias2,
       int parity) {
    extern __shared__ float sm[];
    float* hbuf = sm + SM_HB;
    float* As   = sm + SM_AS;
    float* Bs   = sm + SM_BS;

    const float* fin  = parity ? g_field2 : g_field;
    float*       fout = parity ? g_field  : g_field2;

    int b  = blockIdx.y;
    int y0 = blockIdx.x * 2;
    int p0 = y0 * 64;
    int tx = threadIdx.x;

    // ---------- Phase 1: conv1 (3x3, 64->128) ----------
    int m1 = (tx >> 4) * 8;        // oc
    int n1 = (tx & 15) * 8;        // px
    u64 acc[8][4] = {};            // [oc][px_pair]
    for (int ic0 = 0; ic0 < 64; ic0 += 4) {
        for (int i = tx; i < 36*128; i += 256) {
            int k = i % 36, m = i / 36;
            As[k*132 + m] = w1[m*576 + ic0*9 + k];
        }
        for (int i = tx; i < 36*128; i += 256) {
            int n = i & 127, k = i >> 7;
            int ici = k / 9, tap = k - ici*9;
            int ky = tap / 3, kx = tap - ky*3;
            int y = y0 + (n >> 6) + ky - 1;
            int x = (n & 63) + kx - 1;
            float v = 0.0f;
            if ((unsigned)y < 64u && (unsigned)x < 64u)
                v = fin[((size_t)(b*64) + ic0 + ici)*HW + y*64 + x];
            Bs[k*132 + n] = v;
        }
        __syncthreads();
        #pragma unroll 4
        for (int kk = 0; kk < 36; kk++) {
            float4 a0 = *(const float4*)&As[kk*132 + m1];
            float4 a1 = *(const float4*)&As[kk*132 + m1 + 4];
            u64 am[8] = {dup2(a0.x),dup2(a0.y),dup2(a0.z),dup2(a0.w),
                         dup2(a1.x),dup2(a1.y),dup2(a1.z),dup2(a1.w)};
            ulonglong2 b01 = *(const ulonglong2*)&Bs[kk*132 + n1];
            ulonglong2 b23 = *(const ulonglong2*)&Bs[kk*132 + n1 + 4];
            u64 bn[4] = {b01.x, b01.y, b23.x, b23.y};
            #pragma unroll
            for (int i2 = 0; i2 < 8; i2++)
                #pragma unroll
                for (int j = 0; j < 4; j++)
                    fma2(acc[i2][j], am[i2], bn[j]);
        }
        __syncthreads();
    }
    // bias + relu -> hbuf[oc][px]
    #pragma unroll
    for (int i2 = 0; i2 < 8; i2++) {
        int oc = m1 + i2;
        float bias = bias1[oc];
        float2 q0 = f2u(acc[i2][0]), q1 = f2u(acc[i2][1]);
        float2 q2 = f2u(acc[i2][2]), q3 = f2u(acc[i2][3]);
        float4 v0 = make_float4(fmaxf(q0.x+bias,0.f), fmaxf(q0.y+bias,0.f),
                                fmaxf(q1.x+bias,0.f), fmaxf(q1.y+bias,0.f));
        float4 v1 = make_float4(fmaxf(q2.x+bias,0.f), fmaxf(q2.y+bias,0.f),
                                fmaxf(q3.x+bias,0.f), fmaxf(q3.y+bias,0.f));
        *(float4*)&hbuf[oc*132 + n1]     = v0;
        *(float4*)&hbuf[oc*132 + n1 + 4] = v1;
    }
    __syncthreads();

    // ---------- Phase 2: conv2 (1x1, 128->64) + bias + residual ----------
    int m2 = (tx >> 5) * 8;        // c
    int n2 = (tx & 31) * 4;        // px
    u64 acc2[4][4] = {};           // [c_pair][px]
    for (int k0 = 0; k0 < 128; k0 += 32) {
        for (int i = tx; i < 32*64; i += 256) {
            int k = i & 31, c = i >> 5;
            As[k*68 + c] = w2[c*128 + k0 + k];
        }
        __syncthreads();
        #pragma unroll 8
        for (int kk = 0; kk < 32; kk++) {
            ulonglong2 a01 = *(const ulonglong2*)&As[kk*68 + m2];
            ulonglong2 a23 = *(const ulonglong2*)&As[kk*68 + m2 + 4];
            u64 ap[4] = {a01.x, a01.y, a23.x, a23.y};
            float4 bv = *(const float4*)&hbuf[(k0+kk)*132 + n2];
            u64 bd[4] = {dup2(bv.x), dup2(bv.y), dup2(bv.z), dup2(bv.w)};
            #pragma unroll
            for (int p = 0; p < 4; p++)
                #pragma unroll
                for (int j = 0; j < 4; j++)
                    fma2(acc2[p][j], ap[p], bd[j]);
        }
        __syncthreads();
    }
    #pragma unroll
    for (int p = 0; p < 4; p++) {
        float2 q0 = f2u(acc2[p][0]), q1 = f2u(acc2[p][1]);
        float2 q2 = f2u(acc2[p][2]), q3 = f2u(acc2[p][3]);
        int c0 = m2 + 2*p;
        float bA = bias2[c0], bB = bias2[c0+1];
        size_t offA = ((size_t)(b*64) + c0)*HW + p0 + n2;
        size_t offB = offA + HW;
        float4 rA = *(const float4*)&fin[offA];
        float4 rB = *(const float4*)&fin[offB];
        *(float4*)&fout[offA] = make_float4(q0.x+bA+rA.x, q1.x+bA+rA.y,
                                            q2.x+bA+rA.z, q3.x+bA+rA.w);
        *(float4*)&fout[offB] = make_float4(q0.y+bB+rB.x, q1.y+bB+rB.y,
                                            q2.y+bB+rB.z, q3.y+bB+rB.w);
    }
}

// ---- K5: gather. sampled[b](L x 64) = (gyo ⊗ gxo) * field^T ----
__global__ void __launch_bounds__(256) k_gather() {
    __shared__ float As[64][68];    // [k=w][l]
    __shared__ float Bs[64][68];    // [k=w][c]
    int b  = blockIdx.y;
    int l0 = blockIdx.x * 64;
    int tx = threadIdx.x;
    int m_base = (tx >> 4) * 4;     // l
    int n_base = (tx & 15) * 4;     // c
    u64 acc[4][2] = {};             // [l][c_pair]
    for (int h = 0; h < 64; h++) {
        for (int i = tx; i < 64*64; i += 256) {
            int w = i & 63, l = i >> 6;
            float gy = g_gyo[(b*L_ + l0 + l)*64 + h];
            float gx = g_gxo[(b*L_ + l0 + l)*64 + w];
            As[w][l] = gy * gx;
        }
        for (int i = tx; i < 64*64; i += 256) {
            int w = i & 63, c = i >> 6;
            Bs[w][c] = g_field2[((size_t)(b*64) + c)*HW + h*64 + w];
        }
        __syncthreads();
        #pragma unroll 4
        for (int kk = 0; kk < 64; kk++) {
            float4 a = *(const float4*)&As[kk][m_base];
            u64 ad[4] = {dup2(a.x), dup2(a.y), dup2(a.z), dup2(a.w)};
            ulonglong2 bp = *(const ulonglong2*)&Bs[kk][n_base];
            u64 bn[2] = {bp.x, bp.y};
            #pragma unroll
            for (int i2 = 0; i2 < 4; i2++)
                #pragma unroll
                for (int j = 0; j < 2; j++)
                    fma2(acc[i2][j], ad[i2], bn[j]);
        }
        __syncthreads();
    }
    #pragma unroll
    for (int i2 = 0; i2 < 4; i2++) {
        float2 q0 = f2u(acc[i2][0]), q1 = f2u(acc[i2][1]);
        *(float4*)&g_sampled[((size_t)(b*L_) + l0 + m_base + i2)*64 + n_base]
            = make_float4(q0.x, q0.y, q1.x, q1.y);
    }
}

// ---- K6: tokens_out = sampled @ W_from_field^T  (16384x512, K=64) ----
__global__ void __launch_bounds__(256)
k_out(const float* __restrict__ Wf, float* __restrict__ out) {
    __shared__ float As[64][68];    // [c][m=l]
    __shared__ float Bs[64][68];    // [c][e]
    int m0 = blockIdx.x * 64;
    int e0 = blockIdx.y * 64;
    int tx = threadIdx.x;
    int m_base = (tx >> 4) * 4;
    int n_base = (tx & 15) * 4;
    u64 acc[4][2] = {};
    for (int i = tx; i < 64*64; i += 256) {
        int c = i & 63, m = i >> 6;
        As[c][m] = g_sampled[(size_t)(m0+m)*64 + c];
    }
    for (int i = tx; i < 64*64; i += 256) {
        int c = i & 63, e = i >> 6;
        Bs[c][e] = Wf[(e0+e)*64 + c];
    }
    __syncthreads();
    #pragma unroll 4
    for (int kk = 0; kk < 64; kk++) {
        float4 a = *(const float4*)&As[kk][m_base];
        u64 ad[4] = {dup2(a.x), dup2(a.y), dup2(a.z), dup2(a.w)};
        ulonglong2 bp = *(const ulonglong2*)&Bs[kk][n_base];
        u64 bn[2] = {bp.x, bp.y};
        #pragma unroll
        for (int i2 = 0; i2 < 4; i2++)
            #pragma unroll
            for (int j = 0; j < 2; j++)
                fma2(acc[i2][j], ad[i2], bn[j]);
    }
    #pragma unroll
    for (int i2 = 0; i2 < 4; i2++) {
        float2 q0 = f2u(acc[i2][0]), q1 = f2u(acc[i2][1]);
        *(float4*)&out[(size_t)(m0+m_base+i2)*512 + e0 + n_base]
            = make_float4(q0.x, q0.y, q1.x, q1.y);
    }
}

// ------------------------------ launch -----------------------------------
extern "C" void kernel_launch(void* const* d_in, const int* in_sizes, int n_in,
                              void* d_out, int out_size) {
    const float* tokens     = (const float*)d_in[0];
    const float* positions  = (const float*)d_in[1];
    const float* W_to_field = (const float*)d_in[2];
    const float* W_from_field = (const float*)d_in[3];
    const float* conv1_w    = (const float*)d_in[4];
    const float* conv1_b    = (const float*)d_in[5];
    const float* conv2_w    = (const float*)d_in[6];
    const float* conv2_b    = (const float*)d_in[7];
    const float* log_sigma  = (const float*)d_in[8];
    float* out = (float*)d_out;

    const int smem_bytes = SM_TOTAL_FLOATS * 4;   // 105,600 B
    cudaFuncSetAttribute(k_step, cudaFuncAttributeMaxDynamicSharedMemorySize,
                         smem_bytes);

    k_gauss<<<B_*L_, 64>>>(positions, log_sigma);
    k_proj<<<(B_*L_)/128, 256>>>(tokens, W_to_field);
    k_scatter<<<dim3(32, B_), 256>>>();
    for (int s = 0; s < STEPS_; s++) {
        k_step<<<dim3(32, B_), 256, smem_bytes>>>(conv1_w, conv1_b,
                                                  conv2_w, conv2_b, s & 1);
    }
    k_gather<<<dim3(32, B_), 256>>>();
    k_out<<<dim3((B_*L_)/64, 8), 256>>>(W_from_field, out);
}

// round 9
// speedup vs baseline: 1.2768x; 1.2768x over previous
#include <cuda_runtime.h>
#include <cuda_bf16.h>
#include <math.h>
#include <stdint.h>

#define B_ 8
#define L_ 2048
#define E_ 512
#define D_ 64
#define HW 4096
#define STEPS_ 5

typedef unsigned long long u64;

// ---------------- packed fp32x2 (FFMA2) helpers ----------------
__device__ __forceinline__ u64 dup2(float x) {
    u64 r; asm("mov.b64 %0, {%1, %1};" : "=l"(r) : "f"(x)); return r;
}
__device__ __forceinline__ void fma2(u64& d, u64 a, u64 b) {
    asm("fma.rn.f32x2 %0, %1, %2, %0;" : "+l"(d) : "l"(a), "l"(b));
}
__device__ __forceinline__ float2 f2u(u64 v) {
    float2 f; asm("mov.b64 {%0, %1}, %2;" : "=f"(f.x), "=f"(f.y) : "l"(v)); return f;
}

// ---------------- smem / mma helpers ----------------
__device__ __forceinline__ uint32_t smem_u32(const void* p) {
    uint32_t a;
    asm("{ .reg .u64 t; cvta.to.shared.u64 t, %1; cvt.u32.u64 %0, t; }"
        : "=r"(a) : "l"(p));
    return a;
}
__device__ __forceinline__ uint32_t lds32(uint32_t a) {
    uint32_t v; asm volatile("ld.shared.b32 %0, [%1];" : "=r"(v) : "r"(a)); return v;
}
__device__ __forceinline__ void sts32w(uint32_t a, uint32_t v) {
    asm volatile("st.shared.b32 [%0], %1;" :: "r"(a), "r"(v));
}
__device__ __forceinline__ void sts16(uint32_t a, unsigned short v) {
    asm volatile("st.shared.b16 [%0], %1;" :: "r"(a), "h"(v));
}
// mma.sync m16n8k16 bf16 -> f32 (base-target HMMA, no 'a' features)
__device__ __forceinline__ void mma_bf16(float* d, const uint32_t* a,
                                         uint32_t b0, uint32_t b1) {
    asm volatile(
        "mma.sync.aligned.m16n8k16.row.col.f32.bf16.bf16.f32 "
        "{%0,%1,%2,%3}, {%4,%5,%6,%7}, {%8,%9}, {%0,%1,%2,%3};"
        : "+f"(d[0]), "+f"(d[1]), "+f"(d[2]), "+f"(d[3])
        : "r"(a[0]), "r"(a[1]), "r"(a[2]), "r"(a[3]), "r"(b0), "r"(b1));
}
// split float pair -> packed bf16x2 (hi) + packed bf16x2 (lo)
__device__ __forceinline__ void split2(float a0, float a1, uint32_t& hi, uint32_t& lo) {
    __nv_bfloat162 h = __floats2bfloat162_rn(a0, a1);
    float r0 = a0 - __bfloat162float(h.x);
    float r1 = a1 - __bfloat162float(h.y);
    __nv_bfloat162 l = __floats2bfloat162_rn(r0, r1);
    hi = *reinterpret_cast<uint32_t*>(&h);
    lo = *reinterpret_cast<uint32_t*>(&l);
}

// ---------------- scratch (device globals) ----------------
__device__ float g_gyi[B_*L_*64];
__device__ float g_gxi[B_*L_*64];
__device__ float g_gyo[B_*L_*64];
__device__ float g_gxo[B_*L_*64];
__device__ float g_proj[B_*L_*D_];
__device__ float g_field[B_*D_*HW];
__device__ float g_field2[B_*D_*HW];
__device__ float g_sampled[B_*L_*D_];
__device__ __align__(16) __nv_bfloat16 g_w1h[128*576];
__device__ __align__(16) __nv_bfloat16 g_w1l[128*576];
__device__ __align__(16) __nv_bfloat16 g_w2h[64*128];
__device__ __align__(16) __nv_bfloat16 g_w2l[64*128];

// ---------------- K-1: pre-split weights to bf16 hi/lo ----------------
__global__ void k_split_w(const float* __restrict__ w1, const float* __restrict__ w2) {
    int i = blockIdx.x * 256 + threadIdx.x;
    if (i < 128*576) {
        float v = w1[i];
        __nv_bfloat16 h = __float2bfloat16(v);
        g_w1h[i] = h;
        g_w1l[i] = __float2bfloat16(v - __bfloat162float(h));
    }
    if (i < 64*128) {
        float v = w2[i];
        __nv_bfloat16 h = __float2bfloat16(v);
        g_w2h[i] = h;
        g_w2l[i] = __float2bfloat16(v - __bfloat162float(h));
    }
}

// ---------------- K0: separable gaussians ----------------
__global__ void k_gauss(const float* __restrict__ pos,
                        const float* __restrict__ log_sigma) {
    int bl = blockIdx.x;
    int t  = threadIdx.x;
    float ls = *log_sigma;
    float si = log1pf(expf(ls)) + 1e-6f;
    float so = 2.0f * si;
    float i2si = 1.0f / (2.0f * si * si);
    float i2so = 1.0f / (2.0f * so * so);
    float py = pos[bl*2+0], px = pos[bl*2+1];
    float d  = (float)t;
    float dy2 = (d - py) * (d - py);
    float dx2 = (d - px) * (d - px);
    float gy  = expf(-dy2 * i2si);
    float gx  = expf(-dx2 * i2si);
    float gyo = expf(-dy2 * i2so);
    float gxo = expf(-dx2 * i2so);
    __shared__ float red[4][64];
    __shared__ float sums[4];
    red[0][t]=gy; red[1][t]=gx; red[2][t]=gyo; red[3][t]=gxo;
    __syncthreads();
    if (t < 4) {
        float s = 0.0f;
        #pragma unroll
        for (int i = 0; i < 64; i++) s += red[t][i];
        sums[t] = s;
    }
    __syncthreads();
    float inv_ni = 1.0f / (sums[0]*sums[1] + 1e-6f);
    float inv_no = 1.0f / (sums[2]*sums[3] + 1e-6f);
    int base = bl*64 + t;
    g_gyi[base] = gy  * inv_ni;
    g_gxi[base] = gx;
    g_gyo[base] = gyo * inv_no;
    g_gxo[base] = gxo;
}

// ---------------- K1: proj (FFMA2) ----------------
__global__ void __launch_bounds__(256)
k_proj(const float* __restrict__ tokens, const float* __restrict__ Wt) {
    __shared__ float As[32][132];
    __shared__ float Bs[32][68];
    int m0 = blockIdx.x * 128;
    int tx = threadIdx.x;
    int m_base = (tx >> 4) * 8;
    int n_base = (tx & 15) * 4;
    u64 acc[4][4] = {};
    for (int k0 = 0; k0 < 512; k0 += 32) {
        for (int i = tx; i < 32*128; i += 256) {
            int e = i & 31, m = i >> 5;
            As[e][m] = tokens[(m0+m)*512 + k0 + e];
        }
        for (int i = tx; i < 32*64; i += 256) {
            int e = i & 31, dch = i >> 5;
            Bs[e][dch] = Wt[dch*512 + k0 + e];
        }
        __syncthreads();
        #pragma unroll 4
        for (int kk = 0; kk < 32; kk++) {
            ulonglong2 a01 = *(const ulonglong2*)&As[kk][m_base];
            ulonglong2 a23 = *(const ulonglong2*)&As[kk][m_base+4];
            u64 ap[4] = {a01.x, a01.y, a23.x, a23.y};
            float4 bv = *(const float4*)&Bs[kk][n_base];
            u64 bd[4] = {dup2(bv.x), dup2(bv.y), dup2(bv.z), dup2(bv.w)};
            #pragma unroll
            for (int p = 0; p < 4; p++)
                #pragma unroll
                for (int j = 0; j < 4; j++)
                    fma2(acc[p][j], ap[p], bd[j]);
        }
        __syncthreads();
    }
    #pragma unroll
    for (int p = 0; p < 4; p++) {
        float2 q0 = f2u(acc[p][0]), q1 = f2u(acc[p][1]);
        float2 q2 = f2u(acc[p][2]), q3 = f2u(acc[p][3]);
        int m = m0 + m_base + 2*p;
        *(float4*)&g_proj[(size_t)m*64 + n_base]     = make_float4(q0.x,q1.x,q2.x,q3.x);
        *(float4*)&g_proj[(size_t)(m+1)*64 + n_base] = make_float4(q0.y,q1.y,q2.y,q3.y);
    }
}

// ------- K2: scatter (FFMA2) -------
__global__ void __launch_bounds__(256) k_scatter() {
    __shared__ float As[32][68];
    __shared__ float Bs[32][132];
    int b  = blockIdx.y;
    int n0 = blockIdx.x * 128;
    int h0 = n0 >> 6;
    int tx = threadIdx.x;
    int m_base = (tx >> 5) * 8;
    int n_base = (tx & 31) * 4;
    u64 acc[4][4] = {};
    for (int l0 = 0; l0 < L_; l0 += 32) {
        for (int i = tx; i < 32*64; i += 256) {
            int c = i & 63, k = i >> 6;
            As[k][c] = g_proj[((size_t)(b*L_) + l0 + k)*64 + c];
        }
        for (int i = tx; i < 32*128; i += 256) {
            int n = i & 127, k = i >> 7;
            int l = l0 + k;
            float gy = g_gyi[(b*L_+l)*64 + h0 + (n >> 6)];
            float gx = g_gxi[(b*L_+l)*64 + (n & 63)];
            Bs[k][n] = gy * gx;
        }
        __syncthreads();
        #pragma unroll 4
        for (int kk = 0; kk < 32; kk++) {
            ulonglong2 a01 = *(const ulonglong2*)&As[kk][m_base];
            ulonglong2 a23 = *(const ulonglong2*)&As[kk][m_base+4];
            u64 ap[4] = {a01.x, a01.y, a23.x, a23.y};
            float4 bv = *(const float4*)&Bs[kk][n_base];
            u64 bd[4] = {dup2(bv.x), dup2(bv.y), dup2(bv.z), dup2(bv.w)};
            #pragma unroll
            for (int p = 0; p < 4; p++)
                #pragma unroll
                for (int j = 0; j < 4; j++)
                    fma2(acc[p][j], ap[p], bd[j]);
        }
        __syncthreads();
    }
    #pragma unroll
    for (int p = 0; p < 4; p++) {
        float2 q0 = f2u(acc[p][0]), q1 = f2u(acc[p][1]);
        float2 q2 = f2u(acc[p][2]), q3 = f2u(acc[p][3]);
        int c = m_base + 2*p;
        *(float4*)&g_field[((size_t)(b*64) + c)*HW + n0 + n_base]
            = make_float4(q0.x,q1.x,q2.x,q3.x);
        *(float4*)&g_field[((size_t)(b*64) + c+1)*HW + n0 + n_base]
            = make_float4(q0.y,q1.y,q2.y,q3.y);
    }
}

// ---- K3: fused conv step via mma.sync bf16-split ----
// Phase 1: C1[px=128][oc=128] = im2col[px][k=576] x W1[oc][k], relu+bias -> hbufT
// Phase 2: C2[px=128][c=64]   = hbufT[px][k=128] x W2[c][k], +bias +residual
#define P1_ST 40
#define H_ST 136
#define SM_IH 0
#define SM_IL 10240
#define SM_WH 20480
#define SM_WL 30720
#define SM_W2H 0
#define SM_W2L 17408
#define SM_HH 40960
#define SM_HL 75776
#define STEP_SMEM 110592

__global__ void __launch_bounds__(256, 2)
k_step(const float* __restrict__ bias1, const float* __restrict__ bias2,
       int parity) {
    extern __shared__ __align__(16) char smem[];
    uint32_t sb = smem_u32(smem);
    const float* fin  = parity ? g_field2 : g_field;
    float*       fout = parity ? g_field  : g_field2;
    int b  = blockIdx.y;
    int y0 = blockIdx.x * 2;
    int p0 = y0 * 64;
    int tx = threadIdx.x;
    int lane = tx & 31, w = tx >> 5;
    int gid = lane >> 2, tig = lane & 3;

    // ---------------- Phase 1 ----------------
    int mw = (w & 3) * 32;   // px base
    int nw = (w >> 2) * 64;  // oc base
    float acc[2][8][4];
    #pragma unroll
    for (int a = 0; a < 2; a++)
        #pragma unroll
        for (int c = 0; c < 8; c++)
            #pragma unroll
            for (int d = 0; d < 4; d++) acc[a][c][d] = 0.0f;

    for (int it = 0; it < 18; it++) {
        int kc0 = it * 32;
        #pragma unroll
        for (int j = 0; j < 16; j++) {
            int i = tx + j * 256;
            int px = i & 127, kc = i >> 7;
            int kap = kc0 + kc;
            int ici = kap / 9, tap = kap - ici * 9;
            int ky = tap / 3, kx = tap - ky * 3;
            int y = y0 + (px >> 6) + ky - 1;
            int x = (px & 63) + kx - 1;
            float v = 0.0f;
            if ((unsigned)y < 64u && (unsigned)x < 64u)
                v = fin[((size_t)(b*64) + ici) * HW + y * 64 + x];
            __nv_bfloat16 h = __float2bfloat16(v);
            __nv_bfloat16 l = __float2bfloat16(v - __bfloat162float(h));
            uint32_t off = (uint32_t)(px * P1_ST + kc) * 2;
            sts16(sb + SM_IH + off, *reinterpret_cast<unsigned short*>(&h));
            sts16(sb + SM_IL + off, *reinterpret_cast<unsigned short*>(&l));
        }
        #pragma unroll
        for (int j = 0; j < 8; j++) {
            int i = tx + j * 256;          // pair 0..2047
            int oc = i >> 4, kp = (i & 15) * 2;
            uint32_t vh = *(const uint32_t*)&g_w1h[oc * 576 + kc0 + kp];
            uint32_t vl = *(const uint32_t*)&g_w1l[oc * 576 + kc0 + kp];
            uint32_t off = (uint32_t)(oc * P1_ST + kp) * 2;
            sts32w(sb + SM_WH + off, vh);
            sts32w(sb + SM_WL + off, vl);
        }
        __syncthreads();
        #pragma unroll
        for (int ks = 0; ks < 2; ks++) {
            int k0 = ks * 16;
            uint32_t ah[2][4], al[2][4];
            #pragma unroll
            for (int mt = 0; mt < 2; mt++) {
                uint32_t ba = sb + SM_IH +
                    (uint32_t)((mw + mt*16 + gid) * P1_ST + k0 + tig*2) * 2;
                ah[mt][0] = lds32(ba);
                ah[mt][1] = lds32(ba + 8*P1_ST*2);
                ah[mt][2] = lds32(ba + 16);
                ah[mt][3] = lds32(ba + 8*P1_ST*2 + 16);
                uint32_t bl_ = ba + (SM_IL - SM_IH);
                al[mt][0] = lds32(bl_);
                al[mt][1] = lds32(bl_ + 8*P1_ST*2);
                al[mt][2] = lds32(bl_ + 16);
                al[mt][3] = lds32(bl_ + 8*P1_ST*2 + 16);
            }
            #pragma unroll
            for (int nt = 0; nt < 8; nt++) {
                uint32_t bb = sb + SM_WH +
                    (uint32_t)((nw + nt*8 + gid) * P1_ST + k0 + tig*2) * 2;
                uint32_t bh0 = lds32(bb), bh1 = lds32(bb + 16);
                uint32_t bl0 = lds32(bb + (SM_WL-SM_WH));
                uint32_t bl1 = lds32(bb + (SM_WL-SM_WH) + 16);
                #pragma unroll
                for (int mt = 0; mt < 2; mt++) {
                    mma_bf16(acc[mt][nt], ah[mt], bh0, bh1);
                    mma_bf16(acc[mt][nt], ah[mt], bl0, bl1);
                    mma_bf16(acc[mt][nt], al[mt], bh0, bh1);
                }
            }
        }
        __syncthreads();
    }
    // epilogue phase1: relu + bias -> hbufT (bf16 hi/lo, [px][oc])
    #pragma unroll
    for (int mt = 0; mt < 2; mt++)
        #pragma unroll
        for (int nt = 0; nt < 8; nt++) {
            float* d = acc[mt][nt];
            int c = nw + nt*8 + tig*2;
            float b0f = bias1[c], b1f = bias1[c+1];
            int r1 = mw + mt*16 + gid;
            float h00 = fmaxf(d[0] + b0f, 0.f), h01 = fmaxf(d[1] + b1f, 0.f);
            float h10 = fmaxf(d[2] + b0f, 0.f), h11 = fmaxf(d[3] + b1f, 0.f);
            uint32_t hi0, lo0, hi1, lo1;
            split2(h00, h01, hi0, lo0);
            split2(h10, h11, hi1, lo1);
            uint32_t o1 = (uint32_t)(r1 * H_ST + c) * 2;
            uint32_t o2 = (uint32_t)((r1+8) * H_ST + c) * 2;
            sts32w(sb + SM_HH + o1, hi0); sts32w(sb + SM_HL + o1, lo0);
            sts32w(sb + SM_HH + o2, hi1); sts32w(sb + SM_HL + o2, lo1);
        }
    // stage W2 into overlay region (pairs)
    #pragma unroll
    for (int j = 0; j < 16; j++) {
        int i = tx + j * 256;              // pair 0..4095
        int c = i >> 6, hp = (i & 63) * 2;
        uint32_t vh = *(const uint32_t*)&g_w2h[c * 128 + hp];
        uint32_t vl = *(const uint32_t*)&g_w2l[c * 128 + hp];
        uint32_t off = (uint32_t)(c * H_ST + hp) * 2;
        sts32w(sb + SM_W2H + off, vh);
        sts32w(sb + SM_W2L + off, vl);
    }
    __syncthreads();

    // ---------------- Phase 2 ----------------
    int mw2 = (w & 3) * 32;   // px base
    int nw2 = (w >> 2) * 32;  // c base
    float acc2[2][4][4];
    #pragma unroll
    for (int a = 0; a < 2; a++)
        #pragma unroll
        for (int c = 0; c < 4; c++)
            #pragma unroll
            for (int d = 0; d < 4; d++) acc2[a][c][d] = 0.0f;
    #pragma unroll
    for (int ks = 0; ks < 8; ks++) {
        int k0 = ks * 16;
        uint32_t ah[2][4], al[2][4];
        #pragma unroll
        for (int mt = 0; mt < 2; mt++) {
            uint32_t ba = sb + SM_HH +
                (uint32_t)((mw2 + mt*16 + gid) * H_ST + k0 + tig*2) * 2;
            ah[mt][0] = lds32(ba);
            ah[mt][1] = lds32(ba + 8*H_ST*2);
            ah[mt][2] = lds32(ba + 16);
            ah[mt][3] = lds32(ba + 8*H_ST*2 + 16);
            uint32_t bl_ = ba + (SM_HL - SM_HH);
            al[mt][0] = lds32(bl_);
            al[mt][1] = lds32(bl_ + 8*H_ST*2);
            al[mt][2] = lds32(bl_ + 16);
            al[mt][3] = lds32(bl_ + 8*H_ST*2 + 16);
        }
        #pragma unroll
        for (int nt = 0; nt < 4; nt++) {
            uint32_t bb = sb + SM_W2H +
                (uint32_t)((nw2 + nt*8 + gid) * H_ST + k0 + tig*2) * 2;
            uint32_t bh0 = lds32(bb), bh1 = lds32(bb + 16);
            uint32_t bl0 = lds32(bb + (SM_W2L-SM_W2H));
            uint32_t bl1 = lds32(bb + (SM_W2L-SM_W2H) + 16);
            #pragma unroll
            for (int mt = 0; mt < 2; mt++) {
                mma_bf16(acc2[mt][nt], ah[mt], bh0, bh1);
                mma_bf16(acc2[mt][nt], ah[mt], bl0, bl1);
                mma_bf16(acc2[mt][nt], al[mt], bh0, bh1);
            }
        }
    }
    // epilogue phase2: + bias + residual -> fout
    #pragma unroll
    for (int mt = 0; mt < 2; mt++)
        #pragma unroll
        for (int nt = 0; nt < 4; nt++) {
            float* d = acc2[mt][nt];
            int c = nw2 + nt*8 + tig*2;
            int r1 = mw2 + mt*16 + gid;
            float b0f = bias2[c], b1f = bias2[c+1];
            size_t base0 = ((size_t)(b*64) + c) * HW + p0;
            size_t base1 = base0 + HW;
            fout[base0 + r1]     = d[0] + b0f + fin[base0 + r1];
            fout[base1 + r1]     = d[1] + b1f + fin[base1 + r1];
            fout[base0 + r1 + 8] = d[2] + b0f + fin[base0 + r1 + 8];
            fout[base1 + r1 + 8] = d[3] + b1f + fin[base1 + r1 + 8];
        }
}

// ---- K5: gather (FFMA2), reads g_field2 ----
__global__ void __launch_bounds__(256) k_gather() {
    __shared__ float As[64][68];
    __shared__ float Bs[64][68];
    int b  = blockIdx.y;
    int l0 = blockIdx.x * 64;
    int tx = threadIdx.x;
    int m_base = (tx >> 4) * 4;
    int n_base = (tx & 15) * 4;
    u64 acc[4][2] = {};
    for (int h = 0; h < 64; h++) {
        for (int i = tx; i < 64*64; i += 256) {
            int ww = i & 63, l = i >> 6;
            float gy = g_gyo[(b*L_ + l0 + l)*64 + h];
            float gx = g_gxo[(b*L_ + l0 + l)*64 + ww];
            As[ww][l] = gy * gx;
        }
        for (int i = tx; i < 64*64; i += 256) {
            int ww = i & 63, c = i >> 6;
            Bs[ww][c] = g_field2[((size_t)(b*64) + c)*HW + h*64 + ww];
        }
        __syncthreads();
        #pragma unroll 4
        for (int kk = 0; kk < 64; kk++) {
            float4 a = *(const float4*)&As[kk][m_base];
            u64 ad[4] = {dup2(a.x), dup2(a.y), dup2(a.z), dup2(a.w)};
            ulonglong2 bp = *(const ulonglong2*)&Bs[kk][n_base];
            u64 bn[2] = {bp.x, bp.y};
            #pragma unroll
            for (int i2 = 0; i2 < 4; i2++)
                #pragma unroll
                for (int j = 0; j < 2; j++)
                    fma2(acc[i2][j], ad[i2], bn[j]);
        }
        __syncthreads();
    }
    #pragma unroll
    for (int i2 = 0; i2 < 4; i2++) {
        float2 q0 = f2u(acc[i2][0]), q1 = f2u(acc[i2][1]);
        *(float4*)&g_sampled[((size_t)(b*L_) + l0 + m_base + i2)*64 + n_base]
            = make_float4(q0.x, q0.y, q1.x, q1.y);
    }
}

// ---- K6: tokens_out = sampled @ W_from_field^T (FFMA2) ----
__global__ void __launch_bounds__(256)
k_out(const float* __restrict__ Wf, float* __restrict__ out) {
    __shared__ float As[64][68];
    __shared__ float Bs[64][68];
    int m0 = blockIdx.x * 64;
    int e0 = blockIdx.y * 64;
    int tx = threadIdx.x;
    int m_base = (tx >> 4) * 4;
    int n_base = (tx & 15) * 4;
    u64 acc[4][2] = {};
    for (int i = tx; i < 64*64; i += 256) {
        int c = i & 63, m = i >> 6;
        As[c][m] = g_sampled[(size_t)(m0+m)*64 + c];
    }
    for (int i = tx; i < 64*64; i += 256) {
        int c = i & 63, e = i >> 6;
        Bs[c][e] = Wf[(e0+e)*64 + c];
    }
    __syncthreads();
    #pragma unroll 4
    for (int kk = 0; kk < 64; kk++) {
        float4 a = *(const float4*)&As[kk][m_base];
        u64 ad[4] = {dup2(a.x), dup2(a.y), dup2(a.z), dup2(a.w)};
        ulonglong2 bp = *(const ulonglong2*)&Bs[kk][n_base];
        u64 bn[2] = {bp.x, bp.y};
        #pragma unroll
        for (int i2 = 0; i2 < 4; i2++)
            #pragma unroll
            for (int j = 0; j < 2; j++)
                fma2(acc[i2][j], ad[i2], bn[j]);
    }
    #pragma unroll
    for (int i2 = 0; i2 < 4; i2++) {
        float2 q0 = f2u(acc[i2][0]), q1 = f2u(acc[i2][1]);
        *(float4*)&out[(size_t)(m0+m_base+i2)*512 + e0 + n_base]
            = make_float4(q0.x, q0.y, q1.x, q1.y);
    }
}

// ------------------------------ launch -----------------------------------
extern "C" void kernel_launch(void* const* d_in, const int* in_sizes, int n_in,
                              void* d_out, int out_size) {
    const float* tokens     = (const float*)d_in[0];
    const float* positions  = (const float*)d_in[1];
    const float* W_to_field = (const float*)d_in[2];
    const float* W_from_field = (const float*)d_in[3];
    const float* conv1_w    = (const float*)d_in[4];
    const float* conv1_b    = (const float*)d_in[5];
    const float* conv2_w    = (const float*)d_in[6];
    const float* conv2_b    = (const float*)d_in[7];
    const float* log_sigma  = (const float*)d_in[8];
    float* out = (float*)d_out;

    cudaFuncSetAttribute(k_step, cudaFuncAttributeMaxDynamicSharedMemorySize,
                         STEP_SMEM);

    k_split_w<<<288, 256>>>(conv1_w, conv2_w);
    k_gauss<<<B_*L_, 64>>>(positions, log_sigma);
    k_proj<<<(B_*L_)/128, 256>>>(tokens, W_to_field);
    k_scatter<<<dim3(32, B_), 256>>>();
    for (int s = 0; s < STEPS_; s++) {
        k_step<<<dim3(32, B_), 256, STEP_SMEM>>>(conv1_b, conv2_b, s & 1);
    }
    k_gather<<<dim3(32, B_), 256>>>();   // FIXED: 32 tiles of 64 rows = 2048 tokens
    k_out<<<dim3((B_*L_)/64, 8), 256>>>(W_from_field, out);
}

// round 10
// speedup vs baseline: 1.4262x; 1.1170x over previous
#include <cuda_runtime.h>
#include <cuda_bf16.h>
#include <math.h>
#include <stdint.h>

#define B_ 8
#define L_ 2048
#define E_ 512
#define D_ 64
#define HW 4096
#define STEPS_ 5

typedef unsigned long long u64;

// ---------------- packed fp32x2 (FFMA2) helpers ----------------
__device__ __forceinline__ u64 dup2(float x) {
    u64 r; asm("mov.b64 %0, {%1, %1};" : "=l"(r) : "f"(x)); return r;
}
__device__ __forceinline__ void fma2(u64& d, u64 a, u64 b) {
    asm("fma.rn.f32x2 %0, %1, %2, %0;" : "+l"(d) : "l"(a), "l"(b));
}
__device__ __forceinline__ float2 f2u(u64 v) {
    float2 f; asm("mov.b64 {%0, %1}, %2;" : "=f"(f.x), "=f"(f.y) : "l"(v)); return f;
}

// ---------------- smem / mma helpers ----------------
__device__ __forceinline__ uint32_t smem_u32(const void* p) {
    uint32_t a;
    asm("{ .reg .u64 t; cvta.to.shared.u64 t, %1; cvt.u32.u64 %0, t; }"
        : "=r"(a) : "l"(p));
    return a;
}
__device__ __forceinline__ uint32_t lds32(uint32_t a) {
    uint32_t v; asm volatile("ld.shared.b32 %0, [%1];" : "=r"(v) : "r"(a)); return v;
}
__device__ __forceinline__ void sts32w(uint32_t a, uint32_t v) {
    asm volatile("st.shared.b32 [%0], %1;" :: "r"(a), "r"(v));
}
__device__ __forceinline__ void sts16(uint32_t a, unsigned short v) {
    asm volatile("st.shared.b16 [%0], %1;" :: "r"(a), "h"(v));
}
// mma.sync m16n8k16 bf16 -> f32
__device__ __forceinline__ void mma_bf16(float* d, const uint32_t* a,
                                         uint32_t b0, uint32_t b1) {
    asm volatile(
        "mma.sync.aligned.m16n8k16.row.col.f32.bf16.bf16.f32 "
        "{%0,%1,%2,%3}, {%4,%5,%6,%7}, {%8,%9}, {%0,%1,%2,%3};"
        : "+f"(d[0]), "+f"(d[1]), "+f"(d[2]), "+f"(d[3])
        : "r"(a[0]), "r"(a[1]), "r"(a[2]), "r"(a[3]), "r"(b0), "r"(b1));
}
__device__ __forceinline__ void split2(float a0, float a1, uint32_t& hi, uint32_t& lo) {
    __nv_bfloat162 h = __floats2bfloat162_rn(a0, a1);
    float r0 = a0 - __bfloat162float(h.x);
    float r1 = a1 - __bfloat162float(h.y);
    __nv_bfloat162 l = __floats2bfloat162_rn(r0, r1);
    hi = *reinterpret_cast<uint32_t*>(&h);
    lo = *reinterpret_cast<uint32_t*>(&l);
}

// ---------------- scratch (device globals) ----------------
__device__ float g_gyi[B_*L_*64];
__device__ float g_gxi[B_*L_*64];
__device__ float g_gyo[B_*L_*64];
__device__ float g_gxo[B_*L_*64];
__device__ float g_proj[B_*L_*D_];
__device__ float g_field[B_*D_*HW];
__device__ float g_field2[B_*D_*HW];
__device__ float g_sampled[B_*L_*D_];
__device__ __align__(16) __nv_bfloat16 g_w1h[128*576];
__device__ __align__(16) __nv_bfloat16 g_w1l[128*576];
__device__ __align__(16) __nv_bfloat16 g_w2h[64*128];
__device__ __align__(16) __nv_bfloat16 g_w2l[64*128];

// ---------------- K-1: pre-split weights to bf16 hi/lo ----------------
__global__ void k_split_w(const float* __restrict__ w1, const float* __restrict__ w2) {
    int i = blockIdx.x * 256 + threadIdx.x;
    if (i < 128*576) {
        float v = w1[i];
        __nv_bfloat16 h = __float2bfloat16(v);
        g_w1h[i] = h;
        g_w1l[i] = __float2bfloat16(v - __bfloat162float(h));
    }
    if (i < 64*128) {
        float v = w2[i];
        __nv_bfloat16 h = __float2bfloat16(v);
        g_w2h[i] = h;
        g_w2l[i] = __float2bfloat16(v - __bfloat162float(h));
    }
}

// ---------------- K0: separable gaussians ----------------
__global__ void k_gauss(const float* __restrict__ pos,
                        const float* __restrict__ log_sigma) {
    int bl = blockIdx.x;
    int t  = threadIdx.x;
    float ls = *log_sigma;
    float si = log1pf(expf(ls)) + 1e-6f;
    float so = 2.0f * si;
    float i2si = 1.0f / (2.0f * si * si);
    float i2so = 1.0f / (2.0f * so * so);
    float py = pos[bl*2+0], px = pos[bl*2+1];
    float d  = (float)t;
    float dy2 = (d - py) * (d - py);
    float dx2 = (d - px) * (d - px);
    float gy  = expf(-dy2 * i2si);
    float gx  = expf(-dx2 * i2si);
    float gyo = expf(-dy2 * i2so);
    float gxo = expf(-dx2 * i2so);
    __shared__ float red[4][64];
    __shared__ float sums[4];
    red[0][t]=gy; red[1][t]=gx; red[2][t]=gyo; red[3][t]=gxo;
    __syncthreads();
    if (t < 4) {
        float s = 0.0f;
        #pragma unroll
        for (int i = 0; i < 64; i++) s += red[t][i];
        sums[t] = s;
    }
    __syncthreads();
    float inv_ni = 1.0f / (sums[0]*sums[1] + 1e-6f);
    float inv_no = 1.0f / (sums[2]*sums[3] + 1e-6f);
    int base = bl*64 + t;
    g_gyi[base] = gy  * inv_ni;
    g_gxi[base] = gx;
    g_gyo[base] = gyo * inv_no;
    g_gxo[base] = gxo;
}

// ---------------- K1: proj (FFMA2) ----------------
__global__ void __launch_bounds__(256)
k_proj(const float* __restrict__ tokens, const float* __restrict__ Wt) {
    __shared__ float As[32][132];
    __shared__ float Bs[32][68];
    int m0 = blockIdx.x * 128;
    int tx = threadIdx.x;
    int m_base = (tx >> 4) * 8;
    int n_base = (tx & 15) * 4;
    u64 acc[4][4] = {};
    for (int k0 = 0; k0 < 512; k0 += 32) {
        for (int i = tx; i < 32*128; i += 256) {
            int e = i & 31, m = i >> 5;
            As[e][m] = tokens[(m0+m)*512 + k0 + e];
        }
        for (int i = tx; i < 32*64; i += 256) {
            int e = i & 31, dch = i >> 5;
            Bs[e][dch] = Wt[dch*512 + k0 + e];
        }
        __syncthreads();
        #pragma unroll 4
        for (int kk = 0; kk < 32; kk++) {
            ulonglong2 a01 = *(const ulonglong2*)&As[kk][m_base];
            ulonglong2 a23 = *(const ulonglong2*)&As[kk][m_base+4];
            u64 ap[4] = {a01.x, a01.y, a23.x, a23.y};
            float4 bv = *(const float4*)&Bs[kk][n_base];
            u64 bd[4] = {dup2(bv.x), dup2(bv.y), dup2(bv.z), dup2(bv.w)};
            #pragma unroll
            for (int p = 0; p < 4; p++)
                #pragma unroll
                for (int j = 0; j < 4; j++)
                    fma2(acc[p][j], ap[p], bd[j]);
        }
        __syncthreads();
    }
    #pragma unroll
    for (int p = 0; p < 4; p++) {
        float2 q0 = f2u(acc[p][0]), q1 = f2u(acc[p][1]);
        float2 q2 = f2u(acc[p][2]), q3 = f2u(acc[p][3]);
        int m = m0 + m_base + 2*p;
        *(float4*)&g_proj[(size_t)m*64 + n_base]     = make_float4(q0.x,q1.x,q2.x,q3.x);
        *(float4*)&g_proj[(size_t)(m+1)*64 + n_base] = make_float4(q0.y,q1.y,q2.y,q3.y);
    }
}

// ------- K2: scatter via mma.sync bf16-split -------
// D[px=128][c=64] = sum_l A[px][l]*B[c][l], K=2048 in 64 chunks of 32.
#define SC_ST 40
#define SC_AH 0
#define SC_AL 10240
#define SC_BH 20480
#define SC_BL 25600

__global__ void __launch_bounds__(256) k_scatter() {
    __shared__ __align__(16) char smem[30720];
    uint32_t sb = smem_u32(smem);
    int b  = blockIdx.y;
    int n0 = blockIdx.x * 128;
    int h0 = blockIdx.x * 2;
    int tx = threadIdx.x;
    int lane = tx & 31, w = tx >> 5;
    int gid = lane >> 2, tig = lane & 3;
    int mw = (w & 3) * 32;   // px base
    int nw = (w >> 2) * 32;  // c base
    float acc[2][4][4];
    #pragma unroll
    for (int a = 0; a < 2; a++)
        #pragma unroll
        for (int c = 0; c < 4; c++)
            #pragma unroll
            for (int d = 0; d < 4; d++) acc[a][c][d] = 0.0f;

    for (int ch = 0; ch < 64; ch++) {
        int l0 = ch * 32;
        // stage A[px][kc]: gaussian outer product, bf16 hi/lo (thread owns one l)
        {
            int lp = tx >> 3, sub = tx & 7;   // kc = lp, px = sub*16..+15
            int lg = b * L_ + l0 + lp;
            float gy_a = g_gyi[lg*64 + h0];
            float gy_b = g_gyi[lg*64 + h0 + 1];
            const float* gxr = &g_gxi[(size_t)lg*64];
            #pragma unroll
            for (int i = 0; i < 16; i++) {
                int px = sub * 16 + i;
                float v = ((px < 64) ? gy_a : gy_b) * gxr[px & 63];
                __nv_bfloat16 h = __float2bfloat16(v);
                __nv_bfloat16 l = __float2bfloat16(v - __bfloat162float(h));
                uint32_t off = (uint32_t)(px * SC_ST + lp) * 2;
                sts16(sb + SC_AH + off, *reinterpret_cast<unsigned short*>(&h));
                sts16(sb + SC_AL + off, *reinterpret_cast<unsigned short*>(&l));
            }
        }
        // stage B[c][kc] = proj[l0+kc][c], packed kc pairs
        #pragma unroll
        for (int j = 0; j < 4; j++) {
            int i = tx + j * 256;
            int c = i & 63, kc = (i >> 6) * 2;
            float b0 = g_proj[((size_t)(b*L_) + l0 + kc)*64 + c];
            float b1 = g_proj[((size_t)(b*L_) + l0 + kc + 1)*64 + c];
            uint32_t hi, lo; split2(b0, b1, hi, lo);
            uint32_t off = (uint32_t)(c * SC_ST + kc) * 2;
            sts32w(sb + SC_BH + off, hi);
            sts32w(sb + SC_BL + off, lo);
        }
        __syncthreads();
        #pragma unroll
        for (int ks = 0; ks < 2; ks++) {
            int k0 = ks * 16;
            uint32_t ah[2][4], al[2][4];
            #pragma unroll
            for (int mt = 0; mt < 2; mt++) {
                uint32_t ba = sb + SC_AH +
                    (uint32_t)((mw + mt*16 + gid) * SC_ST + k0 + tig*2) * 2;
                ah[mt][0] = lds32(ba);
                ah[mt][1] = lds32(ba + 8*SC_ST*2);
                ah[mt][2] = lds32(ba + 16);
                ah[mt][3] = lds32(ba + 8*SC_ST*2 + 16);
                uint32_t bl_ = ba + (SC_AL - SC_AH);
                al[mt][0] = lds32(bl_);
                al[mt][1] = lds32(bl_ + 8*SC_ST*2);
                al[mt][2] = lds32(bl_ + 16);
                al[mt][3] = lds32(bl_ + 8*SC_ST*2 + 16);
            }
            #pragma unroll
            for (int nt = 0; nt < 4; nt++) {
                uint32_t bb = sb + SC_BH +
                    (uint32_t)((nw + nt*8 + gid) * SC_ST + k0 + tig*2) * 2;
                uint32_t bh0 = lds32(bb), bh1 = lds32(bb + 16);
                uint32_t bl0 = lds32(bb + (SC_BL-SC_BH));
                uint32_t bl1 = lds32(bb + (SC_BL-SC_BH) + 16);
                #pragma unroll
                for (int mt = 0; mt < 2; mt++) {
                    mma_bf16(acc[mt][nt], ah[mt], bh0, bh1);
                    mma_bf16(acc[mt][nt], ah[mt], bl0, bl1);
                    mma_bf16(acc[mt][nt], al[mt], bh0, bh1);
                }
            }
        }
        __syncthreads();
    }
    // epilogue: field[(b*64+c)*HW + n0 + px]
    #pragma unroll
    for (int mt = 0; mt < 2; mt++)
        #pragma unroll
        for (int nt = 0; nt < 4; nt++) {
            float* d = acc[mt][nt];
            int c  = nw + nt*8 + tig*2;
            int r1 = mw + mt*16 + gid;
            size_t base0 = ((size_t)(b*64) + c) * HW + n0;
            size_t base1 = base0 + HW;
            g_field[base0 + r1]     = d[0];
            g_field[base1 + r1]     = d[1];
            g_field[base0 + r1 + 8] = d[2];
            g_field[base1 + r1 + 8] = d[3];
        }
}

// ---- K3: fused conv step via mma.sync bf16-split (unchanged from R9) ----
#define P1_ST 40
#define H_ST 136
#define SM_IH 0
#define SM_IL 10240
#define SM_WH 20480
#define SM_WL 30720
#define SM_W2H 0
#define SM_W2L 17408
#define SM_HH 40960
#define SM_HL 75776
#define STEP_SMEM 110592

__global__ void __launch_bounds__(256, 2)
k_step(const float* __restrict__ bias1, const float* __restrict__ bias2,
       int parity) {
    extern __shared__ __align__(16) char smem[];
    uint32_t sb = smem_u32(smem);
    const float* fin  = parity ? g_field2 : g_field;
    float*       fout = parity ? g_field  : g_field2;
    int b  = blockIdx.y;
    int y0 = blockIdx.x * 2;
    int p0 = y0 * 64;
    int tx = threadIdx.x;
    int lane = tx & 31, w = tx >> 5;
    int gid = lane >> 2, tig = lane & 3;

    int mw = (w & 3) * 32;
    int nw = (w >> 2) * 64;
    float acc[2][8][4];
    #pragma unroll
    for (int a = 0; a < 2; a++)
        #pragma unroll
        for (int c = 0; c < 8; c++)
            #pragma unroll
            for (int d = 0; d < 4; d++) acc[a][c][d] = 0.0f;

    for (int it = 0; it < 18; it++) {
        int kc0 = it * 32;
        #pragma unroll
        for (int j = 0; j < 16; j++) {
            int i = tx + j * 256;
            int px = i & 127, kc = i >> 7;
            int kap = kc0 + kc;
            int ici = kap / 9, tap = kap - ici * 9;
            int ky = tap / 3, kx = tap - ky * 3;
            int y = y0 + (px >> 6) + ky - 1;
            int x = (px & 63) + kx - 1;
            float v = 0.0f;
            if ((unsigned)y < 64u && (unsigned)x < 64u)
                v = fin[((size_t)(b*64) + ici) * HW + y * 64 + x];
            __nv_bfloat16 h = __float2bfloat16(v);
            __nv_bfloat16 l = __float2bfloat16(v - __bfloat162float(h));
            uint32_t off = (uint32_t)(px * P1_ST + kc) * 2;
            sts16(sb + SM_IH + off, *reinterpret_cast<unsigned short*>(&h));
            sts16(sb + SM_IL + off, *reinterpret_cast<unsigned short*>(&l));
        }
        #pragma unroll
        for (int j = 0; j < 8; j++) {
            int i = tx + j * 256;
            int oc = i >> 4, kp = (i & 15) * 2;
            uint32_t vh = *(const uint32_t*)&g_w1h[oc * 576 + kc0 + kp];
            uint32_t vl = *(const uint32_t*)&g_w1l[oc * 576 + kc0 + kp];
            uint32_t off = (uint32_t)(oc * P1_ST + kp) * 2;
            sts32w(sb + SM_WH + off, vh);
            sts32w(sb + SM_WL + off, vl);
        }
        __syncthreads();
        #pragma unroll
        for (int ks = 0; ks < 2; ks++) {
            int k0 = ks * 16;
            uint32_t ah[2][4], al[2][4];
            #pragma unroll
            for (int mt = 0; mt < 2; mt++) {
                uint32_t ba = sb + SM_IH +
                    (uint32_t)((mw + mt*16 + gid) * P1_ST + k0 + tig*2) * 2;
                ah[mt][0] = lds32(ba);
                ah[mt][1] = lds32(ba + 8*P1_ST*2);
                ah[mt][2] = lds32(ba + 16);
                ah[mt][3] = lds32(ba + 8*P1_ST*2 + 16);
                uint32_t bl_ = ba + (SM_IL - SM_IH);
                al[mt][0] = lds32(bl_);
                al[mt][1] = lds32(bl_ + 8*P1_ST*2);
                al[mt][2] = lds32(bl_ + 16);
                al[mt][3] = lds32(bl_ + 8*P1_ST*2 + 16);
            }
            #pragma unroll
            for (int nt = 0; nt < 8; nt++) {
                uint32_t bb = sb + SM_WH +
                    (uint32_t)((nw + nt*8 + gid) * P1_ST + k0 + tig*2) * 2;
                uint32_t bh0 = lds32(bb), bh1 = lds32(bb + 16);
                uint32_t bl0 = lds32(bb + (SM_WL-SM_WH));
                uint32_t bl1 = lds32(bb + (SM_WL-SM_WH) + 16);
                #pragma unroll
                for (int mt = 0; mt < 2; mt++) {
                    mma_bf16(acc[mt][nt], ah[mt], bh0, bh1);
                    mma_bf16(acc[mt][nt], ah[mt], bl0, bl1);
                    mma_bf16(acc[mt][nt], al[mt], bh0, bh1);
                }
            }
        }
        __syncthreads();
    }
    #pragma unroll
    for (int mt = 0; mt < 2; mt++)
        #pragma unroll
        for (int nt = 0; nt < 8; nt++) {
            float* d = acc[mt][nt];
            int c = nw + nt*8 + tig*2;
            float b0f = bias1[c], b1f = bias1[c+1];
            int r1 = mw + mt*16 + gid;
            float h00 = fmaxf(d[0] + b0f, 0.f), h01 = fmaxf(d[1] + b1f, 0.f);
            float h10 = fmaxf(d[2] + b0f, 0.f), h11 = fmaxf(d[3] + b1f, 0.f);
            uint32_t hi0, lo0, hi1, lo1;
            split2(h00, h01, hi0, lo0);
            split2(h10, h11, hi1, lo1);
            uint32_t o1 = (uint32_t)(r1 * H_ST + c) * 2;
            uint32_t o2 = (uint32_t)((r1+8) * H_ST + c) * 2;
            sts32w(sb + SM_HH + o1, hi0); sts32w(sb + SM_HL + o1, lo0);
            sts32w(sb + SM_HH + o2, hi1); sts32w(sb + SM_HL + o2, lo1);
        }
    #pragma unroll
    for (int j = 0; j < 16; j++) {
        int i = tx + j * 256;
        int c = i >> 6, hp = (i & 63) * 2;
        uint32_t vh = *(const uint32_t*)&g_w2h[c * 128 + hp];
        uint32_t vl = *(const uint32_t*)&g_w2l[c * 128 + hp];
        uint32_t off = (uint32_t)(c * H_ST + hp) * 2;
        sts32w(sb + SM_W2H + off, vh);
        sts32w(sb + SM_W2L + off, vl);
    }
    __syncthreads();

    int mw2 = (w & 3) * 32;
    int nw2 = (w >> 2) * 32;
    float acc2[2][4][4];
    #pragma unroll
    for (int a = 0; a < 2; a++)
        #pragma unroll
        for (int c = 0; c < 4; c++)
            #pragma unroll
            for (int d = 0; d < 4; d++) acc2[a][c][d] = 0.0f;
    #pragma unroll
    for (int ks = 0; ks < 8; ks++) {
        int k0 = ks * 16;
        uint32_t ah[2][4], al[2][4];
        #pragma unroll
        for (int mt = 0; mt < 2; mt++) {
            uint32_t ba = sb + SM_HH +
                (uint32_t)((mw2 + mt*16 + gid) * H_ST + k0 + tig*2) * 2;
            ah[mt][0] = lds32(ba);
            ah[mt][1] = lds32(ba + 8*H_ST*2);
            ah[mt][2] = lds32(ba + 16);
            ah[mt][3] = lds32(ba + 8*H_ST*2 + 16);
            uint32_t bl_ = ba + (SM_HL - SM_HH);
            al[mt][0] = lds32(bl_);
            al[mt][1] = lds32(bl_ + 8*H_ST*2);
            al[mt][2] = lds32(bl_ + 16);
            al[mt][3] = lds32(bl_ + 8*H_ST*2 + 16);
        }
        #pragma unroll
        for (int nt = 0; nt < 4; nt++) {
            uint32_t bb = sb + SM_W2H +
                (uint32_t)((nw2 + nt*8 + gid) * H_ST + k0 + tig*2) * 2;
            uint32_t bh0 = lds32(bb), bh1 = lds32(bb + 16);
            uint32_t bl0 = lds32(bb + (SM_W2L-SM_W2H));
            uint32_t bl1 = lds32(bb + (SM_W2L-SM_W2H) + 16);
            #pragma unroll
            for (int mt = 0; mt < 2; mt++) {
                mma_bf16(acc2[mt][nt], ah[mt], bh0, bh1);
                mma_bf16(acc2[mt][nt], ah[mt], bl0, bl1);
                mma_bf16(acc2[mt][nt], al[mt], bh0, bh1);
            }
        }
    }
    #pragma unroll
    for (int mt = 0; mt < 2; mt++)
        #pragma unroll
        for (int nt = 0; nt < 4; nt++) {
            float* d = acc2[mt][nt];
            int c = nw2 + nt*8 + tig*2;
            int r1 = mw2 + mt*16 + gid;
            float b0f = bias2[c], b1f = bias2[c+1];
            size_t base0 = ((size_t)(b*64) + c) * HW + p0;
            size_t base1 = base0 + HW;
            fout[base0 + r1]     = d[0] + b0f + fin[base0 + r1];
            fout[base1 + r1]     = d[1] + b1f + fin[base1 + r1];
            fout[base0 + r1 + 8] = d[2] + b0f + fin[base0 + r1 + 8];
            fout[base1 + r1 + 8] = d[3] + b1f + fin[base1 + r1 + 8];
        }
}

// ---- K5: gather via mma.sync bf16-split ----
// D[l=64][c=64] = sum_hw A[l][hw]*B[c][hw], K=4096 in 64 chunks (one h row).
#define GA_ST 72
#define GA_AH 0
#define GA_AL 9216
#define GA_BH 18432
#define GA_BL 27648

__global__ void __launch_bounds__(256) k_gather() {
    __shared__ __align__(16) char smem[36864];
    uint32_t sb = smem_u32(smem);
    int b  = blockIdx.y;
    int l0 = blockIdx.x * 64;
    int tx = threadIdx.x;
    int lane = tx & 31, w = tx >> 5;
    int gid = lane >> 2, tig = lane & 3;
    int mw = (w & 3) * 16;   // l base (1 m-tile per warp)
    int nw = (w >> 2) * 32;  // c base
    float acc[4][4];
    #pragma unroll
    for (int c = 0; c < 4; c++)
        #pragma unroll
        for (int d = 0; d < 4; d++) acc[c][d] = 0.0f;

    for (int h = 0; h < 64; h++) {
        // stage A[l][w] = gyo[l][h]*gxo[l][w], packed w pairs
        {
            int l = tx >> 2, w0 = (tx & 3) * 16;
            int lg = b * L_ + l0 + l;
            float gy = g_gyo[lg*64 + h];
            const float* gxr = &g_gxo[(size_t)lg*64];
            #pragma unroll
            for (int j = 0; j < 16; j += 2) {
                int ww = w0 + j;
                float2 g = *(const float2*)&gxr[ww];
                uint32_t hi, lo; split2(gy * g.x, gy * g.y, hi, lo);
                uint32_t off = (uint32_t)(l * GA_ST + ww) * 2;
                sts32w(sb + GA_AH + off, hi);
                sts32w(sb + GA_AL + off, lo);
            }
        }
        // stage B[c][w] = field2[c][h*64+w], packed w pairs
        {
            int c = tx >> 2, w0 = (tx & 3) * 16;
            const float* fr = &g_field2[((size_t)(b*64) + c)*HW + h*64];
            #pragma unroll
            for (int j = 0; j < 16; j += 2) {
                int ww = w0 + j;
                float2 g = *(const float2*)&fr[ww];
                uint32_t hi, lo; split2(g.x, g.y, hi, lo);
                uint32_t off = (uint32_t)(c * GA_ST + ww) * 2;
                sts32w(sb + GA_BH + off, hi);
                sts32w(sb + GA_BL + off, lo);
            }
        }
        __syncthreads();
        #pragma unroll
        for (int ks = 0; ks < 4; ks++) {
            int k0 = ks * 16;
            uint32_t ah[4], al[4];
            uint32_t ba = sb + GA_AH +
                (uint32_t)((mw + gid) * GA_ST + k0 + tig*2) * 2;
            ah[0] = lds32(ba);
            ah[1] = lds32(ba + 8*GA_ST*2);
            ah[2] = lds32(ba + 16);
            ah[3] = lds32(ba + 8*GA_ST*2 + 16);
            uint32_t bl_ = ba + (GA_AL - GA_AH);
            al[0] = lds32(bl_);
            al[1] = lds32(bl_ + 8*GA_ST*2);
            al[2] = lds32(bl_ + 16);
            al[3] = lds32(bl_ + 8*GA_ST*2 + 16);
            #pragma unroll
            for (int nt = 0; nt < 4; nt++) {
                uint32_t bb = sb + GA_BH +
                    (uint32_t)((nw + nt*8 + gid) * GA_ST + k0 + tig*2) * 2;
                uint32_t bh0 = lds32(bb), bh1 = lds32(bb + 16);
                uint32_t bl0 = lds32(bb + (GA_BL-GA_BH));
                uint32_t bl1 = lds32(bb + (GA_BL-GA_BH) + 16);
                mma_bf16(acc[nt], ah, bh0, bh1);
                mma_bf16(acc[nt], ah, bl0, bl1);
                mma_bf16(acc[nt], al, bh0, bh1);
            }
        }
        __syncthreads();
    }
    // epilogue: sampled[(b*L + l0 + r)*64 + c]
    #pragma unroll
    for (int nt = 0; nt < 4; nt++) {
        float* d = acc[nt];
        int c = nw + nt*8 + tig*2;
        int r = mw + gid;
        size_t base0 = ((size_t)(b*L_) + l0 + r) * 64 + c;
        size_t base1 = ((size_t)(b*L_) + l0 + r + 8) * 64 + c;
        g_sampled[base0]     = d[0];
        g_sampled[base0 + 1] = d[1];
        g_sampled[base1]     = d[2];
        g_sampled[base1 + 1] = d[3];
    }
}

// ---- K6: tokens_out = sampled @ W_from_field^T (FFMA2) ----
__global__ void __launch_bounds__(256)
k_out(const float* __restrict__ Wf, float* __restrict__ out) {
    __shared__ float As[64][68];
    __shared__ float Bs[64][68];
    int m0 = blockIdx.x * 64;
    int e0 = blockIdx.y * 64;
    int tx = threadIdx.x;
    int m_base = (tx >> 4) * 4;
    int n_base = (tx & 15) * 4;
    u64 acc[4][2] = {};
    for (int i = tx; i < 64*64; i += 256) {
        int c = i & 63, m = i >> 6;
        As[c][m] = g_sampled[(size_t)(m0+m)*64 + c];
    }
    for (int i = tx; i < 64*64; i += 256) {
        int c = i & 63, e = i >> 6;
        Bs[c][e] = Wf[(e0+e)*64 + c];
    }
    __syncthreads();
    #pragma unroll 4
    for (int kk = 0; kk < 64; kk++) {
        float4 a = *(const float4*)&As[kk][m_base];
        u64 ad[4] = {dup2(a.x), dup2(a.y), dup2(a.z), dup2(a.w)};
        ulonglong2 bp = *(const ulonglong2*)&Bs[kk][n_base];
        u64 bn[2] = {bp.x, bp.y};
        #pragma unroll
        for (int i2 = 0; i2 < 4; i2++)
            #pragma unroll
            for (int j = 0; j < 2; j++)
                fma2(acc[i2][j], ad[i2], bn[j]);
    }
    #pragma unroll
    for (int i2 = 0; i2 < 4; i2++) {
        float2 q0 = f2u(acc[i2][0]), q1 = f2u(acc[i2][1]);
        *(float4*)&out[(size_t)(m0+m_base+i2)*512 + e0 + n_base]
            = make_float4(q0.x, q0.y, q1.x, q1.y);
    }
}

// ------------------------------ launch -----------------------------------
extern "C" void kernel_launch(void* const* d_in, const int* in_sizes, int n_in,
                              void* d_out, int out_size) {
    const float* tokens     = (const float*)d_in[0];
    const float* positions  = (const float*)d_in[1];
    const float* W_to_field = (const float*)d_in[2];
    const float* W_from_field = (const float*)d_in[3];
    const float* conv1_w    = (const float*)d_in[4];
    const float* conv1_b    = (const float*)d_in[5];
    const float* conv2_w    = (const float*)d_in[6];
    const float* conv2_b    = (const float*)d_in[7];
    const float* log_sigma  = (const float*)d_in[8];
    float* out = (float*)d_out;

    cudaFuncSetAttribute(k_step, cudaFuncAttributeMaxDynamicSharedMemorySize,
                         STEP_SMEM);

    k_split_w<<<288, 256>>>(conv1_w, conv2_w);
    k_gauss<<<B_*L_, 64>>>(positions, log_sigma);
    k_proj<<<(B_*L_)/128, 256>>>(tokens, W_to_field);
    k_scatter<<<dim3(32, B_), 256>>>();
    for (int s = 0; s < STEPS_; s++) {
        k_step<<<dim3(32, B_), 256, STEP_SMEM>>>(conv1_b, conv2_b, s & 1);
    }
    k_gather<<<dim3(32, B_), 256>>>();
    k_out<<<dim3((B_*L_)/64, 8), 256>>>(W_from_field, out);
}

// round 11
// speedup vs baseline: 1.4892x; 1.0442x over previous
#include <cuda_runtime.h>
#include <cuda_bf16.h>
#include <math.h>
#include <stdint.h>

#define B_ 8
#define L_ 2048
#define E_ 512
#define D_ 64
#define HW 4096
#define STEPS_ 5

typedef unsigned long long u64;

// ---------------- packed fp32x2 (FFMA2) helpers ----------------
__device__ __forceinline__ u64 dup2(float x) {
    u64 r; asm("mov.b64 %0, {%1, %1};" : "=l"(r) : "f"(x)); return r;
}
__device__ __forceinline__ void fma2(u64& d, u64 a, u64 b) {
    asm("fma.rn.f32x2 %0, %1, %2, %0;" : "+l"(d) : "l"(a), "l"(b));
}
__device__ __forceinline__ float2 f2u(u64 v) {
    float2 f; asm("mov.b64 {%0, %1}, %2;" : "=f"(f.x), "=f"(f.y) : "l"(v)); return f;
}

// ---------------- smem / mma helpers ----------------
__device__ __forceinline__ uint32_t smem_u32(const void* p) {
    uint32_t a;
    asm("{ .reg .u64 t; cvta.to.shared.u64 t, %1; cvt.u32.u64 %0, t; }"
        : "=r"(a) : "l"(p));
    return a;
}
__device__ __forceinline__ void sts32w(uint32_t a, uint32_t v) {
    asm volatile("st.shared.b32 [%0], %1;" :: "r"(a), "r"(v));
}
__device__ __forceinline__ void sts16(uint32_t a, unsigned short v) {
    asm volatile("st.shared.b16 [%0], %1;" :: "r"(a), "h"(v));
}
// ldmatrix: warp-collective fragment loads
__device__ __forceinline__ void ldsm_x4(uint32_t* r, uint32_t addr) {
    asm volatile("ldmatrix.sync.aligned.m8n8.x4.shared.b16 {%0,%1,%2,%3}, [%4];"
        : "=r"(r[0]), "=r"(r[1]), "=r"(r[2]), "=r"(r[3]) : "r"(addr));
}
__device__ __forceinline__ void ldsm_x2(uint32_t* r, uint32_t addr) {
    asm volatile("ldmatrix.sync.aligned.m8n8.x2.shared.b16 {%0,%1}, [%2];"
        : "=r"(r[0]), "=r"(r[1]) : "r"(addr));
}
// lane-dependent ldmatrix source addresses (ST in bf16 elements)
__device__ __forceinline__ uint32_t lm_a_addr(uint32_t sbase, int mrow, int k0,
                                              int ST, int lane) {
    return sbase + (uint32_t)((mrow + (lane & 15)) * ST + k0 + ((lane >> 4) << 3)) * 2;
}
__device__ __forceinline__ uint32_t lm_b_addr(uint32_t sbase, int nrow, int k0,
                                              int ST, int lane) {
    return sbase + (uint32_t)((nrow + (lane & 7)) * ST + k0 + (((lane >> 3) & 1) << 3)) * 2;
}
// mma.sync m16n8k16 bf16 -> f32
__device__ __forceinline__ void mma_bf16(float* d, const uint32_t* a,
                                         uint32_t b0, uint32_t b1) {
    asm volatile(
        "mma.sync.aligned.m16n8k16.row.col.f32.bf16.bf16.f32 "
        "{%0,%1,%2,%3}, {%4,%5,%6,%7}, {%8,%9}, {%0,%1,%2,%3};"
        : "+f"(d[0]), "+f"(d[1]), "+f"(d[2]), "+f"(d[3])
        : "r"(a[0]), "r"(a[1]), "r"(a[2]), "r"(a[3]), "r"(b0), "r"(b1));
}
__device__ __forceinline__ void split2(float a0, float a1, uint32_t& hi, uint32_t& lo) {
    __nv_bfloat162 h = __floats2bfloat162_rn(a0, a1);
    float r0 = a0 - __bfloat162float(h.x);
    float r1 = a1 - __bfloat162float(h.y);
    __nv_bfloat162 l = __floats2bfloat162_rn(r0, r1);
    hi = *reinterpret_cast<uint32_t*>(&h);
    lo = *reinterpret_cast<uint32_t*>(&l);
}

// ---------------- scratch (device globals) ----------------
__device__ float g_gyi[B_*L_*64];
__device__ float g_gxi[B_*L_*64];
__device__ float g_gyo[B_*L_*64];
__device__ float g_gxo[B_*L_*64];
__device__ float g_proj[B_*L_*D_];
__device__ float g_field[B_*D_*HW];
__device__ float g_field2[B_*D_*HW];
__device__ float g_sampled[B_*L_*D_];
__device__ __align__(16) __nv_bfloat16 g_w1h[128*576];
__device__ __align__(16) __nv_bfloat16 g_w1l[128*576];
__device__ __align__(16) __nv_bfloat16 g_w2h[64*128];
__device__ __align__(16) __nv_bfloat16 g_w2l[64*128];

// ---------------- K-1: pre-split weights to bf16 hi/lo ----------------
__global__ void k_split_w(const float* __restrict__ w1, const float* __restrict__ w2) {
    int i = blockIdx.x * 256 + threadIdx.x;
    if (i < 128*576) {
        float v = w1[i];
        __nv_bfloat16 h = __float2bfloat16(v);
        g_w1h[i] = h;
        g_w1l[i] = __float2bfloat16(v - __bfloat162float(h));
    }
    if (i < 64*128) {
        float v = w2[i];
        __nv_bfloat16 h = __float2bfloat16(v);
        g_w2h[i] = h;
        g_w2l[i] = __float2bfloat16(v - __bfloat162float(h));
    }
}

// ---------------- K0: separable gaussians ----------------
__global__ void k_gauss(const float* __restrict__ pos,
                        const float* __restrict__ log_sigma) {
    int bl = blockIdx.x;
    int t  = threadIdx.x;
    float ls = *log_sigma;
    float si = log1pf(expf(ls)) + 1e-6f;
    float so = 2.0f * si;
    float i2si = 1.0f / (2.0f * si * si);
    float i2so = 1.0f / (2.0f * so * so);
    float py = pos[bl*2+0], px = pos[bl*2+1];
    float d  = (float)t;
    float dy2 = (d - py) * (d - py);
    float dx2 = (d - px) * (d - px);
    float gy  = expf(-dy2 * i2si);
    float gx  = expf(-dx2 * i2si);
    float gyo = expf(-dy2 * i2so);
    float gxo = expf(-dx2 * i2so);
    __shared__ float red[4][64];
    __shared__ float sums[4];
    red[0][t]=gy; red[1][t]=gx; red[2][t]=gyo; red[3][t]=gxo;
    __syncthreads();
    if (t < 4) {
        float s = 0.0f;
        #pragma unroll
        for (int i = 0; i < 64; i++) s += red[t][i];
        sums[t] = s;
    }
    __syncthreads();
    float inv_ni = 1.0f / (sums[0]*sums[1] + 1e-6f);
    float inv_no = 1.0f / (sums[2]*sums[3] + 1e-6f);
    int base = bl*64 + t;
    g_gyi[base] = gy  * inv_ni;
    g_gxi[base] = gx;
    g_gyo[base] = gyo * inv_no;
    g_gxo[base] = gxo;
}

// ---------------- K1: proj (FFMA2) ----------------
__global__ void __launch_bounds__(256)
k_proj(const float* __restrict__ tokens, const float* __restrict__ Wt) {
    __shared__ float As[32][132];
    __shared__ float Bs[32][68];
    int m0 = blockIdx.x * 128;
    int tx = threadIdx.x;
    int m_base = (tx >> 4) * 8;
    int n_base = (tx & 15) * 4;
    u64 acc[4][4] = {};
    for (int k0 = 0; k0 < 512; k0 += 32) {
        for (int i = tx; i < 32*128; i += 256) {
            int e = i & 31, m = i >> 5;
            As[e][m] = tokens[(m0+m)*512 + k0 + e];
        }
        for (int i = tx; i < 32*64; i += 256) {
            int e = i & 31, dch = i >> 5;
            Bs[e][dch] = Wt[dch*512 + k0 + e];
        }
        __syncthreads();
        #pragma unroll 4
        for (int kk = 0; kk < 32; kk++) {
            ulonglong2 a01 = *(const ulonglong2*)&As[kk][m_base];
            ulonglong2 a23 = *(const ulonglong2*)&As[kk][m_base+4];
            u64 ap[4] = {a01.x, a01.y, a23.x, a23.y};
            float4 bv = *(const float4*)&Bs[kk][n_base];
            u64 bd[4] = {dup2(bv.x), dup2(bv.y), dup2(bv.z), dup2(bv.w)};
            #pragma unroll
            for (int p = 0; p < 4; p++)
                #pragma unroll
                for (int j = 0; j < 4; j++)
                    fma2(acc[p][j], ap[p], bd[j]);
        }
        __syncthreads();
    }
    #pragma unroll
    for (int p = 0; p < 4; p++) {
        float2 q0 = f2u(acc[p][0]), q1 = f2u(acc[p][1]);
        float2 q2 = f2u(acc[p][2]), q3 = f2u(acc[p][3]);
        int m = m0 + m_base + 2*p;
        *(float4*)&g_proj[(size_t)m*64 + n_base]     = make_float4(q0.x,q1.x,q2.x,q3.x);
        *(float4*)&g_proj[(size_t)(m+1)*64 + n_base] = make_float4(q0.y,q1.y,q2.y,q3.y);
    }
}

// ------- K2: scatter via mma.sync + ldmatrix -------
// D[px=128][c=64] = sum_l A[px][l]*B[c][l], K=2048 in 64 chunks of 32.
#define SC_ST 40
#define SC_AH 0
#define SC_AL 10240
#define SC_BH 20480
#define SC_BL 25600

__global__ void __launch_bounds__(256) k_scatter() {
    __shared__ __align__(16) char smem[30720];
    uint32_t sb = smem_u32(smem);
    int b  = blockIdx.y;
    int n0 = blockIdx.x * 128;
    int h0 = blockIdx.x * 2;
    int tx = threadIdx.x;
    int lane = tx & 31, w = tx >> 5;
    int gid = lane >> 2, tig = lane & 3;
    int mw = (w & 3) * 32;   // px base
    int nw = (w >> 2) * 32;  // c base
    float acc[2][4][4];
    #pragma unroll
    for (int a = 0; a < 2; a++)
        #pragma unroll
        for (int c = 0; c < 4; c++)
            #pragma unroll
            for (int d = 0; d < 4; d++) acc[a][c][d] = 0.0f;

    for (int ch = 0; ch < 64; ch++) {
        int l0 = ch * 32;
        // stage A[px][l]: outer product, l-pairs packed into 32-bit stores
        {
            int lp = (tx & 15) * 2;   // l pair base
            int pg = tx >> 4;         // 16 groups of 8 px
            int lg = b * L_ + l0 + lp;
            float gy0a = g_gyi[lg*64 + h0],     gy0b = g_gyi[lg*64 + h0 + 1];
            float gy1a = g_gyi[(lg+1)*64 + h0], gy1b = g_gyi[(lg+1)*64 + h0 + 1];
            const float* gx0r = &g_gxi[(size_t)lg*64];
            const float* gx1r = gx0r + 64;
            #pragma unroll
            for (int i = 0; i < 8; i++) {
                int px = pg * 8 + i;
                int ww = px & 63;
                float v0 = ((px < 64) ? gy0a : gy0b) * gx0r[ww];
                float v1 = ((px < 64) ? gy1a : gy1b) * gx1r[ww];
                uint32_t hi, lo; split2(v0, v1, hi, lo);
                uint32_t off = (uint32_t)(px * SC_ST + lp) * 2;
                sts32w(sb + SC_AH + off, hi);
                sts32w(sb + SC_AL + off, lo);
            }
        }
        // stage B[c][kc] = proj[l0+kc][c], packed kc pairs
        #pragma unroll
        for (int j = 0; j < 4; j++) {
            int i = tx + j * 256;
            int c = i & 63, kc = (i >> 6) * 2;
            float b0 = g_proj[((size_t)(b*L_) + l0 + kc)*64 + c];
            float b1 = g_proj[((size_t)(b*L_) + l0 + kc + 1)*64 + c];
            uint32_t hi, lo; split2(b0, b1, hi, lo);
            uint32_t off = (uint32_t)(c * SC_ST + kc) * 2;
            sts32w(sb + SC_BH + off, hi);
            sts32w(sb + SC_BL + off, lo);
        }
        __syncthreads();
        #pragma unroll
        for (int ks = 0; ks < 2; ks++) {
            int k0 = ks * 16;
            uint32_t ah[2][4], al[2][4];
            #pragma unroll
            for (int mt = 0; mt < 2; mt++) {
                uint32_t ad = lm_a_addr(sb + SC_AH, mw + mt*16, k0, SC_ST, lane);
                ldsm_x4(ah[mt], ad);
                ldsm_x4(al[mt], ad + (SC_AL - SC_AH));
            }
            #pragma unroll
            for (int nt = 0; nt < 4; nt++) {
                uint32_t bd_ = lm_b_addr(sb + SC_BH, nw + nt*8, k0, SC_ST, lane);
                uint32_t bh[2], bl[2];
                ldsm_x2(bh, bd_);
                ldsm_x2(bl, bd_ + (SC_BL - SC_BH));
                #pragma unroll
                for (int mt = 0; mt < 2; mt++) {
                    mma_bf16(acc[mt][nt], ah[mt], bh[0], bh[1]);
                    mma_bf16(acc[mt][nt], ah[mt], bl[0], bl[1]);
                    mma_bf16(acc[mt][nt], al[mt], bh[0], bh[1]);
                }
            }
        }
        __syncthreads();
    }
    #pragma unroll
    for (int mt = 0; mt < 2; mt++)
        #pragma unroll
        for (int nt = 0; nt < 4; nt++) {
            float* d = acc[mt][nt];
            int c  = nw + nt*8 + tig*2;
            int r1 = mw + mt*16 + gid;
            size_t base0 = ((size_t)(b*64) + c) * HW + n0;
            size_t base1 = base0 + HW;
            g_field[base0 + r1]     = d[0];
            g_field[base1 + r1]     = d[1];
            g_field[base0 + r1 + 8] = d[2];
            g_field[base1 + r1 + 8] = d[3];
        }
}

// ---- K3: fused conv step via mma.sync + ldmatrix ----
#define P1_ST 40
#define H_ST 136
#define SM_IH 0
#define SM_IL 10240
#define SM_WH 20480
#define SM_WL 30720
#define SM_W2H 0
#define SM_W2L 17408
#define SM_HH 40960
#define SM_HL 75776
#define STEP_SMEM 110592

__global__ void __launch_bounds__(256, 2)
k_step(const float* __restrict__ bias1, const float* __restrict__ bias2,
       int parity) {
    extern __shared__ __align__(16) char smem[];
    uint32_t sb = smem_u32(smem);
    const float* fin  = parity ? g_field2 : g_field;
    float*       fout = parity ? g_field  : g_field2;
    int b  = blockIdx.y;
    int y0 = blockIdx.x * 2;
    int p0 = y0 * 64;
    int tx = threadIdx.x;
    int lane = tx & 31, w = tx >> 5;
    int gid = lane >> 2, tig = lane & 3;

    int mw = (w & 3) * 32;
    int nw = (w >> 2) * 64;
    float acc[2][8][4];
    #pragma unroll
    for (int a = 0; a < 2; a++)
        #pragma unroll
        for (int c = 0; c < 8; c++)
            #pragma unroll
            for (int d = 0; d < 4; d++) acc[a][c][d] = 0.0f;

    for (int it = 0; it < 18; it++) {
        int kc0 = it * 32;
        #pragma unroll
        for (int j = 0; j < 16; j++) {
            int i = tx + j * 256;
            int px = i & 127, kc = i >> 7;
            int kap = kc0 + kc;
            int ici = kap / 9, tap = kap - ici * 9;
            int ky = tap / 3, kx = tap - ky * 3;
            int y = y0 + (px >> 6) + ky - 1;
            int x = (px & 63) + kx - 1;
            float v = 0.0f;
            if ((unsigned)y < 64u && (unsigned)x < 64u)
                v = fin[((size_t)(b*64) + ici) * HW + y * 64 + x];
            __nv_bfloat16 h = __float2bfloat16(v);
            __nv_bfloat16 l = __float2bfloat16(v - __bfloat162float(h));
            uint32_t off = (uint32_t)(px * P1_ST + kc) * 2;
            sts16(sb + SM_IH + off, *reinterpret_cast<unsigned short*>(&h));
            sts16(sb + SM_IL + off, *reinterpret_cast<unsigned short*>(&l));
        }
        #pragma unroll
        for (int j = 0; j < 8; j++) {
            int i = tx + j * 256;
            int oc = i >> 4, kp = (i & 15) * 2;
            uint32_t vh = *(const uint32_t*)&g_w1h[oc * 576 + kc0 + kp];
            uint32_t vl = *(const uint32_t*)&g_w1l[oc * 576 + kc0 + kp];
            uint32_t off = (uint32_t)(oc * P1_ST + kp) * 2;
            sts32w(sb + SM_WH + off, vh);
            sts32w(sb + SM_WL + off, vl);
        }
        __syncthreads();
        #pragma unroll
        for (int ks = 0; ks < 2; ks++) {
            int k0 = ks * 16;
            uint32_t ah[2][4], al[2][4];
            #pragma unroll
            for (int mt = 0; mt < 2; mt++) {
                uint32_t ad = lm_a_addr(sb + SM_IH, mw + mt*16, k0, P1_ST, lane);
                ldsm_x4(ah[mt], ad);
                ldsm_x4(al[mt], ad + (SM_IL - SM_IH));
            }
            #pragma unroll
            for (int nt = 0; nt < 8; nt++) {
                uint32_t bd_ = lm_b_addr(sb + SM_WH, nw + nt*8, k0, P1_ST, lane);
                uint32_t bh[2], bl[2];
                ldsm_x2(bh, bd_);
                ldsm_x2(bl, bd_ + (SM_WL - SM_WH));
                #pragma unroll
                for (int mt = 0; mt < 2; mt++) {
                    mma_bf16(acc[mt][nt], ah[mt], bh[0], bh[1]);
                    mma_bf16(acc[mt][nt], ah[mt], bl[0], bl[1]);
                    mma_bf16(acc[mt][nt], al[mt], bh[0], bh[1]);
                }
            }
        }
        __syncthreads();
    }
    #pragma unroll
    for (int mt = 0; mt < 2; mt++)
        #pragma unroll
        for (int nt = 0; nt < 8; nt++) {
            float* d = acc[mt][nt];
            int c = nw + nt*8 + tig*2;
            float b0f = bias1[c], b1f = bias1[c+1];
            int r1 = mw + mt*16 + gid;
            float h00 = fmaxf(d[0] + b0f, 0.f), h01 = fmaxf(d[1] + b1f, 0.f);
            float h10 = fmaxf(d[2] + b0f, 0.f), h11 = fmaxf(d[3] + b1f, 0.f);
            uint32_t hi0, lo0, hi1, lo1;
            split2(h00, h01, hi0, lo0);
            split2(h10, h11, hi1, lo1);
            uint32_t o1 = (uint32_t)(r1 * H_ST + c) * 2;
            uint32_t o2 = (uint32_t)((r1+8) * H_ST + c) * 2;
            sts32w(sb + SM_HH + o1, hi0); sts32w(sb + SM_HL + o1, lo0);
            sts32w(sb + SM_HH + o2, hi1); sts32w(sb + SM_HL + o2, lo1);
        }
    #pragma unroll
    for (int j = 0; j < 16; j++) {
        int i = tx + j * 256;
        int c = i >> 6, hp = (i & 63) * 2;
        uint32_t vh = *(const uint32_t*)&g_w2h[c * 128 + hp];
        uint32_t vl = *(const uint32_t*)&g_w2l[c * 128 + hp];
        uint32_t off = (uint32_t)(c * H_ST + hp) * 2;
        sts32w(sb + SM_W2H + off, vh);
        sts32w(sb + SM_W2L + off, vl);
    }
    __syncthreads();

    int mw2 = (w & 3) * 32;
    int nw2 = (w >> 2) * 32;
    float acc2[2][4][4];
    #pragma unroll
    for (int a = 0; a < 2; a++)
        #pragma unroll
        for (int c = 0; c < 4; c++)
            #pragma unroll
            for (int d = 0; d < 4; d++) acc2[a][c][d] = 0.0f;
    #pragma unroll
    for (int ks = 0; ks < 8; ks++) {
        int k0 = ks * 16;
        uint32_t ah[2][4], al[2][4];
        #pragma unroll
        for (int mt = 0; mt < 2; mt++) {
            uint32_t ad = lm_a_addr(sb + SM_HH, mw2 + mt*16, k0, H_ST, lane);
            ldsm_x4(ah[mt], ad);
            ldsm_x4(al[mt], ad + (SM_HL - SM_HH));
        }
        #pragma unroll
        for (int nt = 0; nt < 4; nt++) {
            uint32_t bd_ = lm_b_addr(sb + SM_W2H, nw2 + nt*8, k0, H_ST, lane);
            uint32_t bh[2], bl[2];
            ldsm_x2(bh, bd_);
            ldsm_x2(bl, bd_ + (SM_W2L - SM_W2H));
            #pragma unroll
            for (int mt = 0; mt < 2; mt++) {
                mma_bf16(acc2[mt][nt], ah[mt], bh[0], bh[1]);
                mma_bf16(acc2[mt][nt], ah[mt], bl[0], bl[1]);
                mma_bf16(acc2[mt][nt], al[mt], bh[0], bh[1]);
            }
        }
    }
    #pragma unroll
    for (int mt = 0; mt < 2; mt++)
        #pragma unroll
        for (int nt = 0; nt < 4; nt++) {
            float* d = acc2[mt][nt];
            int c = nw2 + nt*8 + tig*2;
            int r1 = mw2 + mt*16 + gid;
            float b0f = bias2[c], b1f = bias2[c+1];
            size_t base0 = ((size_t)(b*64) + c) * HW + p0;
            size_t base1 = base0 + HW;
            fout[base0 + r1]     = d[0] + b0f + fin[base0 + r1];
            fout[base1 + r1]     = d[1] + b1f + fin[base1 + r1];
            fout[base0 + r1 + 8] = d[2] + b0f + fin[base0 + r1 + 8];
            fout[base1 + r1 + 8] = d[3] + b1f + fin[base1 + r1 + 8];
        }
}

// ---- K5: gather via mma.sync + ldmatrix ----
#define GA_ST 72
#define GA_AH 0
#define GA_AL 9216
#define GA_BH 18432
#define GA_BL 27648

__global__ void __launch_bounds__(256) k_gather() {
    __shared__ __align__(16) char smem[36864];
    uint32_t sb = smem_u32(smem);
    int b  = blockIdx.y;
    int l0 = blockIdx.x * 64;
    int tx = threadIdx.x;
    int lane = tx & 31, w = tx >> 5;
    int gid = lane >> 2, tig = lane & 3;
    int mw = (w & 3) * 16;
    int nw = (w >> 2) * 32;
    float acc[4][4];
    #pragma unroll
    for (int c = 0; c < 4; c++)
        #pragma unroll
        for (int d = 0; d < 4; d++) acc[c][d] = 0.0f;

    for (int h = 0; h < 64; h++) {
        {
            int l = tx >> 2, w0 = (tx & 3) * 16;
            int lg = b * L_ + l0 + l;
            float gy = g_gyo[lg*64 + h];
            const float* gxr = &g_gxo[(size_t)lg*64];
            #pragma unroll
            for (int j = 0; j < 16; j += 2) {
                int ww = w0 + j;
                float2 g = *(const float2*)&gxr[ww];
                uint32_t hi, lo; split2(gy * g.x, gy * g.y, hi, lo);
                uint32_t off = (uint32_t)(l * GA_ST + ww) * 2;
                sts32w(sb + GA_AH + off, hi);
                sts32w(sb + GA_AL + off, lo);
            }
        }
        {
            int c = tx >> 2, w0 = (tx & 3) * 16;
            const float* fr = &g_field2[((size_t)(b*64) + c)*HW + h*64];
            #pragma unroll
            for (int j = 0; j < 16; j += 2) {
                int ww = w0 + j;
                float2 g = *(const float2*)&fr[ww];
                uint32_t hi, lo; split2(g.x, g.y, hi, lo);
                uint32_t off = (uint32_t)(c * GA_ST + ww) * 2;
                sts32w(sb + GA_BH + off, hi);
                sts32w(sb + GA_BL + off, lo);
            }
        }
        __syncthreads();
        #pragma unroll
        for (int ks = 0; ks < 4; ks++) {
            int k0 = ks * 16;
            uint32_t ah[4], al[4];
            uint32_t ad = lm_a_addr(sb + GA_AH, mw, k0, GA_ST, lane);
            ldsm_x4(ah, ad);
            ldsm_x4(al, ad + (GA_AL - GA_AH));
            #pragma unroll
            for (int nt = 0; nt < 4; nt++) {
                uint32_t bd_ = lm_b_addr(sb + GA_BH, nw + nt*8, k0, GA_ST, lane);
                uint32_t bh[2], bl[2];
                ldsm_x2(bh, bd_);
                ldsm_x2(bl, bd_ + (GA_BL - GA_BH));
                mma_bf16(acc[nt], ah, bh[0], bh[1]);
                mma_bf16(acc[nt], ah, bl[0], bl[1]);
                mma_bf16(acc[nt], al, bh[0], bh[1]);
            }
        }
        __syncthreads();
    }
    #pragma unroll
    for (int nt = 0; nt < 4; nt++) {
        float* d = acc[nt];
        int c = nw + nt*8 + tig*2;
        int r = mw + gid;
        size_t base0 = ((size_t)(b*L_) + l0 + r) * 64 + c;
        size_t base1 = ((size_t)(b*L_) + l0 + r + 8) * 64 + c;
        g_sampled[base0]     = d[0];
        g_sampled[base0 + 1] = d[1];
        g_sampled[base1]     = d[2];
        g_sampled[base1 + 1] = d[3];
    }
}

// ---- K6: tokens_out = sampled @ W_from_field^T (FFMA2) ----
__global__ void __launch_bounds__(256)
k_out(const float* __restrict__ Wf, float* __restrict__ out) {
    __shared__ float As[64][68];
    __shared__ float Bs[64][68];
    int m0 = blockIdx.x * 64;
    int e0 = blockIdx.y * 64;
    int tx = threadIdx.x;
    int m_base = (tx >> 4) * 4;
    int n_base = (tx & 15) * 4;
    u64 acc[4][2] = {};
    for (int i = tx; i < 64*64; i += 256) {
        int c = i & 63, m = i >> 6;
        As[c][m] = g_sampled[(size_t)(m0+m)*64 + c];
    }
    for (int i = tx; i < 64*64; i += 256) {
        int c = i & 63, e = i >> 6;
        Bs[c][e] = Wf[(e0+e)*64 + c];
    }
    __syncthreads();
    #pragma unroll 4
    for (int kk = 0; kk < 64; kk++) {
        float4 a = *(const float4*)&As[kk][m_base];
        u64 ad[4] = {dup2(a.x), dup2(a.y), dup2(a.z), dup2(a.w)};
        ulonglong2 bp = *(const ulonglong2*)&Bs[kk][n_base];
        u64 bn[2] = {bp.x, bp.y};
        #pragma unroll
        for (int i2 = 0; i2 < 4; i2++)
            #pragma unroll
            for (int j = 0; j < 2; j++)
                fma2(acc[i2][j], ad[i2], bn[j]);
    }
    #pragma unroll
    for (int i2 = 0; i2 < 4; i2++) {
        float2 q0 = f2u(acc[i2][0]), q1 = f2u(acc[i2][1]);
        *(float4*)&out[(size_t)(m0+m_base+i2)*512 + e0 + n_base]
            = make_float4(q0.x, q0.y, q1.x, q1.y);
    }
}

// ------------------------------ launch -----------------------------------
extern "C" void kernel_launch(void* const* d_in, const int* in_sizes, int n_in,
                              void* d_out, int out_size) {
    const float* tokens     = (const float*)d_in[0];
    const float* positions  = (const float*)d_in[1];
    const float* W_to_field = (const float*)d_in[2];
    const float* W_from_field = (const float*)d_in[3];
    const float* conv1_w    = (const float*)d_in[4];
    const float* conv1_b    = (const float*)d_in[5];
    const float* conv2_w    = (const float*)d_in[6];
    const float* conv2_b    = (const float*)d_in[7];
    const float* log_sigma  = (const float*)d_in[8];
    float* out = (float*)d_out;

    cudaFuncSetAttribute(k_step, cudaFuncAttributeMaxDynamicSharedMemorySize,
                         STEP_SMEM);

    k_split_w<<<288, 256>>>(conv1_w, conv2_w);
    k_gauss<<<B_*L_, 64>>>(positions, log_sigma);
    k_proj<<<(B_*L_)/128, 256>>>(tokens, W_to_field);
    k_scatter<<<dim3(32, B_), 256>>>();
    for (int s = 0; s < STEPS_; s++) {
        k_step<<<dim3(32, B_), 256, STEP_SMEM>>>(conv1_b, conv2_b, s & 1);
    }
    k_gather<<<dim3(32, B_), 256>>>();
    k_out<<<dim3((B_*L_)/64, 8), 256>>>(W_from_field, out);
}

// round 12
// speedup vs baseline: 1.8823x; 1.2640x over previous
#include <cuda_runtime.h>
#include <cuda_bf16.h>
#include <math.h>
#include <stdint.h>

#define B_ 8
#define L_ 2048
#define E_ 512
#define D_ 64
#define HW 4096
#define STEPS_ 5

typedef unsigned long long u64;

// ---------------- packed fp32x2 (FFMA2) helpers ----------------
__device__ __forceinline__ u64 dup2(float x) {
    u64 r; asm("mov.b64 %0, {%1, %1};" : "=l"(r) : "f"(x)); return r;
}
__device__ __forceinline__ void fma2(u64& d, u64 a, u64 b) {
    asm("fma.rn.f32x2 %0, %1, %2, %0;" : "+l"(d) : "l"(a), "l"(b));
}
__device__ __forceinline__ float2 f2u(u64 v) {
    float2 f; asm("mov.b64 {%0, %1}, %2;" : "=f"(f.x), "=f"(f.y) : "l"(v)); return f;
}

// ---------------- smem / mma helpers ----------------
__device__ __forceinline__ uint32_t smem_u32(const void* p) {
    uint32_t a;
    asm("{ .reg .u64 t; cvta.to.shared.u64 t, %1; cvt.u32.u64 %0, t; }"
        : "=r"(a) : "l"(p));
    return a;
}
__device__ __forceinline__ void sts32w(uint32_t a, uint32_t v) {
    asm volatile("st.shared.b32 [%0], %1;" :: "r"(a), "r"(v));
}
__device__ __forceinline__ void sts16(uint32_t a, unsigned short v) {
    asm volatile("st.shared.b16 [%0], %1;" :: "r"(a), "h"(v));
}
__device__ __forceinline__ void ldsm_x4(uint32_t* r, uint32_t addr) {
    asm volatile("ldmatrix.sync.aligned.m8n8.x4.shared.b16 {%0,%1,%2,%3}, [%4];"
        : "=r"(r[0]), "=r"(r[1]), "=r"(r[2]), "=r"(r[3]) : "r"(addr));
}
__device__ __forceinline__ void ldsm_x2(uint32_t* r, uint32_t addr) {
    asm volatile("ldmatrix.sync.aligned.m8n8.x2.shared.b16 {%0,%1}, [%2];"
        : "=r"(r[0]), "=r"(r[1]) : "r"(addr));
}
__device__ __forceinline__ uint32_t lm_a_addr(uint32_t sbase, int mrow, int k0,
                                              int ST, int lane) {
    return sbase + (uint32_t)((mrow + (lane & 15)) * ST + k0 + ((lane >> 4) << 3)) * 2;
}
__device__ __forceinline__ uint32_t lm_b_addr(uint32_t sbase, int nrow, int k0,
                                              int ST, int lane) {
    return sbase + (uint32_t)((nrow + (lane & 7)) * ST + k0 + (((lane >> 3) & 1) << 3)) * 2;
}
__device__ __forceinline__ void mma_bf16(float* d, const uint32_t* a,
                                         uint32_t b0, uint32_t b1) {
    asm volatile(
        "mma.sync.aligned.m16n8k16.row.col.f32.bf16.bf16.f32 "
        "{%0,%1,%2,%3}, {%4,%5,%6,%7}, {%8,%9}, {%0,%1,%2,%3};"
        : "+f"(d[0]), "+f"(d[1]), "+f"(d[2]), "+f"(d[3])
        : "r"(a[0]), "r"(a[1]), "r"(a[2]), "r"(a[3]), "r"(b0), "r"(b1));
}
__device__ __forceinline__ void split2(float a0, float a1, uint32_t& hi, uint32_t& lo) {
    __nv_bfloat162 h = __floats2bfloat162_rn(a0, a1);
    float r0 = a0 - __bfloat162float(h.x);
    float r1 = a1 - __bfloat162float(h.y);
    __nv_bfloat162 l = __floats2bfloat162_rn(r0, r1);
    hi = *reinterpret_cast<uint32_t*>(&h);
    lo = *reinterpret_cast<uint32_t*>(&l);
}

// ---------------- scratch (device globals) ----------------
__device__ float g_gyi[B_*L_*64];
__device__ float g_gyiT[B_*64*L_];   // transposed: [(b*64+h)][l]
__device__ float g_gxi[B_*L_*64];
__device__ float g_gyo[B_*L_*64];
__device__ float g_gxo[B_*L_*64];
__device__ float g_proj[B_*L_*D_];
__device__ float g_field[B_*D_*HW];
__device__ float g_field2[B_*D_*HW];
__device__ float g_sampled[B_*L_*D_];
__device__ __align__(16) __nv_bfloat16 g_w1h[128*576];
__device__ __align__(16) __nv_bfloat16 g_w1l[128*576];
__device__ __align__(16) __nv_bfloat16 g_w2h[64*128];
__device__ __align__(16) __nv_bfloat16 g_w2l[64*128];

// ---------------- K-1: pre-split weights to bf16 hi/lo ----------------
__global__ void k_split_w(const float* __restrict__ w1, const float* __restrict__ w2) {
    int i = blockIdx.x * 256 + threadIdx.x;
    if (i < 128*576) {
        float v = w1[i];
        __nv_bfloat16 h = __float2bfloat16(v);
        g_w1h[i] = h;
        g_w1l[i] = __float2bfloat16(v - __bfloat162float(h));
    }
    if (i < 64*128) {
        float v = w2[i];
        __nv_bfloat16 h = __float2bfloat16(v);
        g_w2h[i] = h;
        g_w2l[i] = __float2bfloat16(v - __bfloat162float(h));
    }
}

// ---------------- K0: separable gaussians ----------------
__global__ void k_gauss(const float* __restrict__ pos,
                        const float* __restrict__ log_sigma) {
    int bl = blockIdx.x;
    int t  = threadIdx.x;
    float ls = *log_sigma;
    float si = log1pf(expf(ls)) + 1e-6f;
    float so = 2.0f * si;
    float i2si = 1.0f / (2.0f * si * si);
    float i2so = 1.0f / (2.0f * so * so);
    float py = pos[bl*2+0], px = pos[bl*2+1];
    float d  = (float)t;
    float dy2 = (d - py) * (d - py);
    float dx2 = (d - px) * (d - px);
    float gy  = expf(-dy2 * i2si);
    float gx  = expf(-dx2 * i2si);
    float gyo = expf(-dy2 * i2so);
    float gxo = expf(-dx2 * i2so);
    __shared__ float red[4][64];
    __shared__ float sums[4];
    red[0][t]=gy; red[1][t]=gx; red[2][t]=gyo; red[3][t]=gxo;
    __syncthreads();
    if (t < 4) {
        float s = 0.0f;
        #pragma unroll
        for (int i = 0; i < 64; i++) s += red[t][i];
        sums[t] = s;
    }
    __syncthreads();
    float inv_ni = 1.0f / (sums[0]*sums[1] + 1e-6f);
    float inv_no = 1.0f / (sums[2]*sums[3] + 1e-6f);
    int base = bl*64 + t;
    float gyn = gy * inv_ni;
    g_gyi[base] = gyn;
    g_gxi[base] = gx;
    g_gyo[base] = gyo * inv_no;
    g_gxo[base] = gxo;
    int b = bl >> 11, l = bl & 2047;
    g_gyiT[((size_t)(b*64) + t)*L_ + l] = gyn;
}

// ---------------- K1: proj (FFMA2) ----------------
__global__ void __launch_bounds__(256)
k_proj(const float* __restrict__ tokens, const float* __restrict__ Wt) {
    __shared__ float As[32][132];
    __shared__ float Bs[32][68];
    int m0 = blockIdx.x * 128;
    int tx = threadIdx.x;
    int m_base = (tx >> 4) * 8;
    int n_base = (tx & 15) * 4;
    u64 acc[4][4] = {};
    for (int k0 = 0; k0 < 512; k0 += 32) {
        for (int i = tx; i < 32*128; i += 256) {
            int e = i & 31, m = i >> 5;
            As[e][m] = tokens[(m0+m)*512 + k0 + e];
        }
        for (int i = tx; i < 32*64; i += 256) {
            int e = i & 31, dch = i >> 5;
            Bs[e][dch] = Wt[dch*512 + k0 + e];
        }
        __syncthreads();
        #pragma unroll 4
        for (int kk = 0; kk < 32; kk++) {
            ulonglong2 a01 = *(const ulonglong2*)&As[kk][m_base];
            ulonglong2 a23 = *(const ulonglong2*)&As[kk][m_base+4];
            u64 ap[4] = {a01.x, a01.y, a23.x, a23.y};
            float4 bv = *(const float4*)&Bs[kk][n_base];
            u64 bd[4] = {dup2(bv.x), dup2(bv.y), dup2(bv.z), dup2(bv.w)};
            #pragma unroll
            for (int p = 0; p < 4; p++)
                #pragma unroll
                for (int j = 0; j < 4; j++)
                    fma2(acc[p][j], ap[p], bd[j]);
        }
        __syncthreads();
    }
    #pragma unroll
    for (int p = 0; p < 4; p++) {
        float2 q0 = f2u(acc[p][0]), q1 = f2u(acc[p][1]);
        float2 q2 = f2u(acc[p][2]), q3 = f2u(acc[p][3]);
        int m = m0 + m_base + 2*p;
        *(float4*)&g_proj[(size_t)m*64 + n_base]     = make_float4(q0.x,q1.x,q2.x,q3.x);
        *(float4*)&g_proj[(size_t)(m+1)*64 + n_base] = make_float4(q0.y,q1.y,q2.y,q3.y);
    }
}

// ------- K2: scatter via mma.sync + ldmatrix, coalesced staging -------
#define SC_ST 40
#define SC_AH 0
#define SC_AL 10240
#define SC_BH 20480
#define SC_BL 25600
#define SC_GX 30720
#define SC_GY (30720 + 32*65*4)
#define SC_SMEM (SC_GY + 64*4)

__global__ void __launch_bounds__(256) k_scatter() {
    __shared__ __align__(16) char smem[SC_SMEM];
    uint32_t sb = smem_u32(smem);
    int b  = blockIdx.y;
    int n0 = blockIdx.x * 128;
    int h0 = blockIdx.x * 2;
    int tx = threadIdx.x;
    int lane = tx & 31, w = tx >> 5;
    int gid = lane >> 2, tig = lane & 3;
    int mw = (w & 3) * 32;
    int nw = (w >> 2) * 32;
    float acc[2][4][4];
    #pragma unroll
    for (int a = 0; a < 2; a++)
        #pragma unroll
        for (int c = 0; c < 4; c++)
            #pragma unroll
            for (int d = 0; d < 4; d++) acc[a][c][d] = 0.0f;

    float* gxs = reinterpret_cast<float*>(smem + SC_GX);   // [32][65]
    float* gys = reinterpret_cast<float*>(smem + SC_GY);   // [32][2]

    for (int ch = 0; ch < 64; ch++) {
        int l0 = ch * 32;
        // phase 1 (coalesced): gx slab -> smem cache, gy pairs, stage B
        #pragma unroll
        for (int j = 0; j < 8; j++) {
            int i = tx + j * 256;
            int l = i >> 6, ww = i & 63;
            gxs[l*65 + ww] = g_gxi[((size_t)(b*L_) + l0 + l)*64 + ww];
        }
        if (tx < 64) {
            int h = tx >> 5, l = tx & 31;
            gys[l*2 + h] = g_gyiT[((size_t)(b*64) + h0 + h)*L_ + l0 + l];
        }
        #pragma unroll
        for (int j = 0; j < 4; j++) {
            int i = tx + j * 256;
            int c = i & 63, kc = (i >> 6) * 2;
            float b0 = g_proj[((size_t)(b*L_) + l0 + kc)*64 + c];
            float b1 = g_proj[((size_t)(b*L_) + l0 + kc + 1)*64 + c];
            uint32_t hi, lo; split2(b0, b1, hi, lo);
            uint32_t off = (uint32_t)(c * SC_ST + kc) * 2;
            sts32w(sb + SC_BH + off, hi);
            sts32w(sb + SC_BL + off, lo);
        }
        __syncthreads();
        // phase 2: build A fragments from smem (conflict-free)
        {
            int lp = (tx & 15) * 2;
            int pg = tx >> 4;
            const float* gx0r = gxs + lp * 65;
            const float* gx1r = gx0r + 65;
            float gy0a = gys[lp*2+0],     gy0b = gys[lp*2+1];
            float gy1a = gys[(lp+1)*2+0], gy1b = gys[(lp+1)*2+1];
            #pragma unroll
            for (int i = 0; i < 8; i++) {
                int px = pg * 8 + i;
                int ww = px & 63;
                float v0 = ((px < 64) ? gy0a : gy0b) * gx0r[ww];
                float v1 = ((px < 64) ? gy1a : gy1b) * gx1r[ww];
                uint32_t hi, lo; split2(v0, v1, hi, lo);
                uint32_t off = (uint32_t)(px * SC_ST + lp) * 2;
                sts32w(sb + SC_AH + off, hi);
                sts32w(sb + SC_AL + off, lo);
            }
        }
        __syncthreads();
        #pragma unroll
        for (int ks = 0; ks < 2; ks++) {
            int k0 = ks * 16;
            uint32_t ah[2][4], al[2][4];
            #pragma unroll
            for (int mt = 0; mt < 2; mt++) {
                uint32_t ad = lm_a_addr(sb + SC_AH, mw + mt*16, k0, SC_ST, lane);
                ldsm_x4(ah[mt], ad);
                ldsm_x4(al[mt], ad + (SC_AL - SC_AH));
            }
            #pragma unroll
            for (int nt = 0; nt < 4; nt++) {
                uint32_t bd_ = lm_b_addr(sb + SC_BH, nw + nt*8, k0, SC_ST, lane);
                uint32_t bh[2], bl[2];
                ldsm_x2(bh, bd_);
                ldsm_x2(bl, bd_ + (SC_BL - SC_BH));
                #pragma unroll
                for (int mt = 0; mt < 2; mt++) {
                    mma_bf16(acc[mt][nt], ah[mt], bh[0], bh[1]);
                    mma_bf16(acc[mt][nt], ah[mt], bl[0], bl[1]);
                    mma_bf16(acc[mt][nt], al[mt], bh[0], bh[1]);
                }
            }
        }
        __syncthreads();
    }
    #pragma unroll
    for (int mt = 0; mt < 2; mt++)
        #pragma unroll
        for (int nt = 0; nt < 4; nt++) {
            float* d = acc[mt][nt];
            int c  = nw + nt*8 + tig*2;
            int r1 = mw + mt*16 + gid;
            size_t base0 = ((size_t)(b*64) + c) * HW + n0;
            size_t base1 = base0 + HW;
            g_field[base0 + r1]     = d[0];
            g_field[base1 + r1]     = d[1];
            g_field[base0 + r1 + 8] = d[2];
            g_field[base1 + r1 + 8] = d[3];
        }
}

// ---- K3: fused conv step via mma.sync + ldmatrix (unchanged) ----
#define P1_ST 40
#define H_ST 136
#define SM_IH 0
#define SM_IL 10240
#define SM_WH 20480
#define SM_WL 30720
#define SM_W2H 0
#define SM_W2L 17408
#define SM_HH 40960
#define SM_HL 75776
#define STEP_SMEM 110592

__global__ void __launch_bounds__(256, 2)
k_step(const float* __restrict__ bias1, const float* __restrict__ bias2,
       int parity) {
    extern __shared__ __align__(16) char smem[];
    uint32_t sb = smem_u32(smem);
    const float* fin  = parity ? g_field2 : g_field;
    float*       fout = parity ? g_field  : g_field2;
    int b  = blockIdx.y;
    int y0 = blockIdx.x * 2;
    int p0 = y0 * 64;
    int tx = threadIdx.x;
    int lane = tx & 31, w = tx >> 5;
    int gid = lane >> 2, tig = lane & 3;

    int mw = (w & 3) * 32;
    int nw = (w >> 2) * 64;
    float acc[2][8][4];
    #pragma unroll
    for (int a = 0; a < 2; a++)
        #pragma unroll
        for (int c = 0; c < 8; c++)
            #pragma unroll
            for (int d = 0; d < 4; d++) acc[a][c][d] = 0.0f;

    for (int it = 0; it < 18; it++) {
        int kc0 = it * 32;
        #pragma unroll
        for (int j = 0; j < 16; j++) {
            int i = tx + j * 256;
            int px = i & 127, kc = i >> 7;
            int kap = kc0 + kc;
            int ici = kap / 9, tap = kap - ici * 9;
            int ky = tap / 3, kx = tap - ky * 3;
            int y = y0 + (px >> 6) + ky - 1;
            int x = (px & 63) + kx - 1;
            float v = 0.0f;
            if ((unsigned)y < 64u && (unsigned)x < 64u)
                v = fin[((size_t)(b*64) + ici) * HW + y * 64 + x];
            __nv_bfloat16 h = __float2bfloat16(v);
            __nv_bfloat16 l = __float2bfloat16(v - __bfloat162float(h));
            uint32_t off = (uint32_t)(px * P1_ST + kc) * 2;
            sts16(sb + SM_IH + off, *reinterpret_cast<unsigned short*>(&h));
            sts16(sb + SM_IL + off, *reinterpret_cast<unsigned short*>(&l));
        }
        #pragma unroll
        for (int j = 0; j < 8; j++) {
            int i = tx + j * 256;
            int oc = i >> 4, kp = (i & 15) * 2;
            uint32_t vh = *(const uint32_t*)&g_w1h[oc * 576 + kc0 + kp];
            uint32_t vl = *(const uint32_t*)&g_w1l[oc * 576 + kc0 + kp];
            uint32_t off = (uint32_t)(oc * P1_ST + kp) * 2;
            sts32w(sb + SM_WH + off, vh);
            sts32w(sb + SM_WL + off, vl);
        }
        __syncthreads();
        #pragma unroll
        for (int ks = 0; ks < 2; ks++) {
            int k0 = ks * 16;
            uint32_t ah[2][4], al[2][4];
            #pragma unroll
            for (int mt = 0; mt < 2; mt++) {
                uint32_t ad = lm_a_addr(sb + SM_IH, mw + mt*16, k0, P1_ST, lane);
                ldsm_x4(ah[mt], ad);
                ldsm_x4(al[mt], ad + (SM_IL - SM_IH));
            }
            #pragma unroll
            for (int nt = 0; nt < 8; nt++) {
                uint32_t bd_ = lm_b_addr(sb + SM_WH, nw + nt*8, k0, P1_ST, lane);
                uint32_t bh[2], bl[2];
                ldsm_x2(bh, bd_);
                ldsm_x2(bl, bd_ + (SM_WL - SM_WH));
                #pragma unroll
                for (int mt = 0; mt < 2; mt++) {
                    mma_bf16(acc[mt][nt], ah[mt], bh[0], bh[1]);
                    mma_bf16(acc[mt][nt], ah[mt], bl[0], bl[1]);
                    mma_bf16(acc[mt][nt], al[mt], bh[0], bh[1]);
                }
            }
        }
        __syncthreads();
    }
    #pragma unroll
    for (int mt = 0; mt < 2; mt++)
        #pragma unroll
        for (int nt = 0; nt < 8; nt++) {
            float* d = acc[mt][nt];
            int c = nw + nt*8 + tig*2;
            float b0f = bias1[c], b1f = bias1[c+1];
            int r1 = mw + mt*16 + gid;
            float h00 = fmaxf(d[0] + b0f, 0.f), h01 = fmaxf(d[1] + b1f, 0.f);
            float h10 = fmaxf(d[2] + b0f, 0.f), h11 = fmaxf(d[3] + b1f, 0.f);
            uint32_t hi0, lo0, hi1, lo1;
            split2(h00, h01, hi0, lo0);
            split2(h10, h11, hi1, lo1);
            uint32_t o1 = (uint32_t)(r1 * H_ST + c) * 2;
            uint32_t o2 = (uint32_t)((r1+8) * H_ST + c) * 2;
            sts32w(sb + SM_HH + o1, hi0); sts32w(sb + SM_HL + o1, lo0);
            sts32w(sb + SM_HH + o2, hi1); sts32w(sb + SM_HL + o2, lo1);
        }
    #pragma unroll
    for (int j = 0; j < 16; j++) {
        int i = tx + j * 256;
        int c = i >> 6, hp = (i & 63) * 2;
        uint32_t vh = *(const uint32_t*)&g_w2h[c * 128 + hp];
        uint32_t vl = *(const uint32_t*)&g_w2l[c * 128 + hp];
        uint32_t off = (uint32_t)(c * H_ST + hp) * 2;
        sts32w(sb + SM_W2H + off, vh);
        sts32w(sb + SM_W2L + off, vl);
    }
    __syncthreads();

    int mw2 = (w & 3) * 32;
    int nw2 = (w >> 2) * 32;
    float acc2[2][4][4];
    #pragma unroll
    for (int a = 0; a < 2; a++)
        #pragma unroll
        for (int c = 0; c < 4; c++)
            #pragma unroll
            for (int d = 0; d < 4; d++) acc2[a][c][d] = 0.0f;
    #pragma unroll
    for (int ks = 0; ks < 8; ks++) {
        int k0 = ks * 16;
        uint32_t ah[2][4], al[2][4];
        #pragma unroll
        for (int mt = 0; mt < 2; mt++) {
            uint32_t ad = lm_a_addr(sb + SM_HH, mw2 + mt*16, k0, H_ST, lane);
            ldsm_x4(ah[mt], ad);
            ldsm_x4(al[mt], ad + (SM_HL - SM_HH));
        }
        #pragma unroll
        for (int nt = 0; nt < 4; nt++) {
            uint32_t bd_ = lm_b_addr(sb + SM_W2H, nw2 + nt*8, k0, H_ST, lane);
            uint32_t bh[2], bl[2];
            ldsm_x2(bh, bd_);
            ldsm_x2(bl, bd_ + (SM_W2L - SM_W2H));
            #pragma unroll
            for (int mt = 0; mt < 2; mt++) {
                mma_bf16(acc2[mt][nt], ah[mt], bh[0], bh[1]);
                mma_bf16(acc2[mt][nt], ah[mt], bl[0], bl[1]);
                mma_bf16(acc2[mt][nt], al[mt], bh[0], bh[1]);
            }
        }
    }
    #pragma unroll
    for (int mt = 0; mt < 2; mt++)
        #pragma unroll
        for (int nt = 0; nt < 4; nt++) {
            float* d = acc2[mt][nt];
            int c = nw2 + nt*8 + tig*2;
            int r1 = mw2 + mt*16 + gid;
            float b0f = bias2[c], b1f = bias2[c+1];
            size_t base0 = ((size_t)(b*64) + c) * HW + p0;
            size_t base1 = base0 + HW;
            fout[base0 + r1]     = d[0] + b0f + fin[base0 + r1];
            fout[base1 + r1]     = d[1] + b1f + fin[base1 + r1];
            fout[base0 + r1 + 8] = d[2] + b0f + fin[base0 + r1 + 8];
            fout[base1 + r1 + 8] = d[3] + b1f + fin[base1 + r1 + 8];
        }
}

// ---- K5: gather via mma.sync + ldmatrix, coalesced staging ----
#define GA_ST 72
#define GA_AH 0
#define GA_AL 9216
#define GA_BH 18432
#define GA_BL 27648

__global__ void __launch_bounds__(256) k_gather() {
    __shared__ __align__(16) char smem[36864];
    uint32_t sb = smem_u32(smem);
    int b  = blockIdx.y;
    int l0 = blockIdx.x * 64;
    int tx = threadIdx.x;
    int lane = tx & 31, w = tx >> 5;
    int gid = lane >> 2, tig = lane & 3;
    int mw = (w & 3) * 16;
    int nw = (w >> 2) * 32;
    float acc[4][4];
    #pragma unroll
    for (int c = 0; c < 4; c++)
        #pragma unroll
        for (int d = 0; d < 4; d++) acc[c][d] = 0.0f;

    for (int h = 0; h < 64; h++) {
        // A rows: warp->row, lane->w (coalesced float2; gy broadcast)
        #pragma unroll
        for (int j = 0; j < 8; j++) {
            int r  = w + j * 8;
            int ww = lane * 2;
            int lg = b * L_ + l0 + r;
            float gy = g_gyo[(size_t)lg*64 + h];
            float2 g = *(const float2*)&g_gxo[(size_t)lg*64 + ww];
            uint32_t hi, lo; split2(gy * g.x, gy * g.y, hi, lo);
            uint32_t off = (uint32_t)(r * GA_ST + ww) * 2;
            sts32w(sb + GA_AH + off, hi);
            sts32w(sb + GA_AL + off, lo);
        }
        // B rows: warp->c row, lane->w (coalesced float2)
        #pragma unroll
        for (int j = 0; j < 8; j++) {
            int r  = w + j * 8;
            int ww = lane * 2;
            float2 g = *(const float2*)&g_field2[((size_t)(b*64) + r)*HW + h*64 + ww];
            uint32_t hi, lo; split2(g.x, g.y, hi, lo);
            uint32_t off = (uint32_t)(r * GA_ST + ww) * 2;
            sts32w(sb + GA_BH + off, hi);
            sts32w(sb + GA_BL + off, lo);
        }
        __syncthreads();
        #pragma unroll
        for (int ks = 0; ks < 4; ks++) {
            int k0 = ks * 16;
            uint32_t ah[4], al[4];
            uint32_t ad = lm_a_addr(sb + GA_AH, mw, k0, GA_ST, lane);
            ldsm_x4(ah, ad);
            ldsm_x4(al, ad + (GA_AL - GA_AH));
            #pragma unroll
            for (int nt = 0; nt < 4; nt++) {
                uint32_t bd_ = lm_b_addr(sb + GA_BH, nw + nt*8, k0, GA_ST, lane);
                uint32_t bh[2], bl[2];
                ldsm_x2(bh, bd_);
                ldsm_x2(bl, bd_ + (GA_BL - GA_BH));
                mma_bf16(acc[nt], ah, bh[0], bh[1]);
                mma_bf16(acc[nt], ah, bl[0], bl[1]);
                mma_bf16(acc[nt], al, bh[0], bh[1]);
            }
        }
        __syncthreads();
    }
    #pragma unroll
    for (int nt = 0; nt < 4; nt++) {
        float* d = acc[nt];
        int c = nw + nt*8 + tig*2;
        int r = mw + gid;
        size_t base0 = ((size_t)(b*L_) + l0 + r) * 64 + c;
        size_t base1 = ((size_t)(b*L_) + l0 + r + 8) * 64 + c;
        g_sampled[base0]     = d[0];
        g_sampled[base0 + 1] = d[1];
        g_sampled[base1]     = d[2];
        g_sampled[base1 + 1] = d[3];
    }
}

// ---- K6: tokens_out = sampled @ W_from_field^T (FFMA2) ----
__global__ void __launch_bounds__(256)
k_out(const float* __restrict__ Wf, float* __restrict__ out) {
    __shared__ float As[64][68];
    __shared__ float Bs[64][68];
    int m0 = blockIdx.x * 64;
    int e0 = blockIdx.y * 64;
    int tx = threadIdx.x;
    int m_base = (tx >> 4) * 4;
    int n_base = (tx & 15) * 4;
    u64 acc[4][2] = {};
    for (int i = tx; i < 64*64; i += 256) {
        int c = i & 63, m = i >> 6;
        As[c][m] = g_sampled[(size_t)(m0+m)*64 + c];
    }
    for (int i = tx; i < 64*64; i += 256) {
        int c = i & 63, e = i >> 6;
        Bs[c][e] = Wf[(e0+e)*64 + c];
    }
    __syncthreads();
    #pragma unroll 4
    for (int kk = 0; kk < 64; kk++) {
        float4 a = *(const float4*)&As[kk][m_base];
        u64 ad[4] = {dup2(a.x), dup2(a.y), dup2(a.z), dup2(a.w)};
        ulonglong2 bp = *(const ulonglong2*)&Bs[kk][n_base];
        u64 bn[2] = {bp.x, bp.y};
        #pragma unroll
        for (int i2 = 0; i2 < 4; i2++)
            #pragma unroll
            for (int j = 0; j < 2; j++)
                fma2(acc[i2][j], ad[i2], bn[j]);
    }
    #pragma unroll
    for (int i2 = 0; i2 < 4; i2++) {
        float2 q0 = f2u(acc[i2][0]), q1 = f2u(acc[i2][1]);
        *(float4*)&out[(size_t)(m0+m_base+i2)*512 + e0 + n_base]
            = make_float4(q0.x, q0.y, q1.x, q1.y);
    }
}

// ------------------------------ launch -----------------------------------
extern "C" void kernel_launch(void* const* d_in, const int* in_sizes, int n_in,
                              void* d_out, int out_size) {
    const float* tokens     = (const float*)d_in[0];
    const float* positions  = (const float*)d_in[1];
    const float* W_to_field = (const float*)d_in[2];
    const float* W_from_field = (const float*)d_in[3];
    const float* conv1_w    = (const float*)d_in[4];
    const float* conv1_b    = (const float*)d_in[5];
    const float* conv2_w    = (const float*)d_in[6];
    const float* conv2_b    = (const float*)d_in[7];
    const float* log_sigma  = (const float*)d_in[8];
    float* out = (float*)d_out;

    cudaFuncSetAttribute(k_step, cudaFuncAttributeMaxDynamicSharedMemorySize,
                         STEP_SMEM);

    k_split_w<<<288, 256>>>(conv1_w, conv2_w);
    k_gauss<<<B_*L_, 64>>>(positions, log_sigma);
    k_proj<<<(B_*L_)/128, 256>>>(tokens, W_to_field);
    k_scatter<<<dim3(32, B_), 256>>>();
    for (int s = 0; s < STEPS_; s++) {
        k_step<<<dim3(32, B_), 256, STEP_SMEM>>>(conv1_b, conv2_b, s & 1);
    }
    k_gather<<<dim3(32, B_), 256>>>();
    k_out<<<dim3((B_*L_)/64, 8), 256>>>(W_from_field, out);
}